// round 3
// baseline (speedup 1.0000x reference)
#include <cuda_runtime.h>
#include <math.h>
#include <stdint.h>

#define Bn  2
#define Tn  2048
#define Cn  1024
#define Hn  16
#define Dn  64
#define En  8
#define HDn 1536
#define BTn (Bn*Tn)          // 4096 tokens

// ---------------- scratch (device globals; no allocations allowed) ----------------
__device__ float g_h[BTn*Cn];                       // rmsnorm output (reused for ffn norm)
__device__ float g_qkv[3*BTn*Cn];                   // q | k | v, each [BT][H*D]
__device__ float g_y[BTn*Cn];                       // attention output
__device__ float g_moe[BTn*Cn];                     // MoE accumulation
__device__ float g_g[(size_t)En*4096*HDn];          // gated hidden per expert row block
__device__ int   g_tok[En*4096];
__device__ float g_gate[En*4096];
__device__ int   g_counts[En];

// ---------------- zero scratch ----------------
__global__ void zero_kernel() {
    int i = blockIdx.x * 256 + threadIdx.x;          // BT*C/4 threads
    ((float4*)g_moe)[i] = make_float4(0.f, 0.f, 0.f, 0.f);
    if (i < En) g_counts[i] = 0;
}

// ---------------- rmsnorm: one block per token ----------------
__global__ __launch_bounds__(256) void rmsnorm_kernel(
    const float* __restrict__ x, const float* __restrict__ w, float* __restrict__ out)
{
    const int t = blockIdx.x;
    const int tid = threadIdx.x;
    const float* xp = x + (size_t)t * Cn;
    float v0 = xp[tid], v1 = xp[tid+256], v2 = xp[tid+512], v3 = xp[tid+768];
    float s = v0*v0 + v1*v1 + v2*v2 + v3*v3;
#pragma unroll
    for (int off = 16; off > 0; off >>= 1) s += __shfl_xor_sync(0xffffffffu, s, off);
    __shared__ float ws[8];
    if ((tid & 31) == 0) ws[tid >> 5] = s;
    __syncthreads();
    float tot = 0.f;
#pragma unroll
    for (int i = 0; i < 8; i++) tot += ws[i];
    const float r = rsqrtf(tot * (1.f/Cn) + 1e-6f);
    float* op = out + (size_t)t * Cn;
    op[tid]     = w[tid]     * v0 * r;
    op[tid+256] = w[tid+256] * v1 * r;
    op[tid+512] = w[tid+512] * v2 * r;
    op[tid+768] = w[tid+768] * v3 * r;
}

// ---------------- generic GEMM: C[M,N] = A[M,K] @ B[N,K]^T (+resid) ----------------
// 128x128 tile, BK=16, 256 threads, 8x8 per thread, 2-stage double buffering.
__global__ __launch_bounds__(256) void gemm_big(
    const float* __restrict__ A,
    const float* __restrict__ B0, const float* __restrict__ B1, const float* __restrict__ B2,
    float* Cbase, size_t cstride,
    const float* __restrict__ resid,
    int Kd, int N)
{
    const int z = blockIdx.z;
    const float* Bm = (z == 0) ? B0 : (z == 1) ? B1 : B2;
    float* Cm = Cbase + (size_t)z * cstride;
    __shared__ float As[2][16][128];
    __shared__ float Bs[2][16][128];
    const int tid = threadIdx.x;
    const int bm = blockIdx.y * 128;
    const int bn = blockIdx.x * 128;
    const int tx = tid & 15, ty = tid >> 4;

    // load indices (two chunks of 256 float4-slots per matrix)
    const int r0 = tid >> 2,             c40 = (tid & 3) << 2;
    const int r1 = (tid + 256) >> 2,     c41 = c40;
    const float* Ap0 = &A [(size_t)(bm + r0)*Kd + c40];
    const float* Ap1 = &A [(size_t)(bm + r1)*Kd + c41];
    const float* Bp0 = &Bm[(size_t)(bn + r0)*Kd + c40];
    const float* Bp1 = &Bm[(size_t)(bn + r1)*Kd + c41];

    float4 ra0, ra1, rb0, rb1;
    float acc[8][8];
#pragma unroll
    for (int i = 0; i < 8; i++)
#pragma unroll
        for (int j = 0; j < 8; j++) acc[i][j] = 0.f;

    // prologue: load tile 0 into buffer 0
    ra0 = *(const float4*)(Ap0);
    ra1 = *(const float4*)(Ap1);
    rb0 = *(const float4*)(Bp0);
    rb1 = *(const float4*)(Bp1);
    As[0][c40+0][r0]=ra0.x; As[0][c40+1][r0]=ra0.y; As[0][c40+2][r0]=ra0.z; As[0][c40+3][r0]=ra0.w;
    As[0][c41+0][r1]=ra1.x; As[0][c41+1][r1]=ra1.y; As[0][c41+2][r1]=ra1.z; As[0][c41+3][r1]=ra1.w;
    Bs[0][c40+0][r0]=rb0.x; Bs[0][c40+1][r0]=rb0.y; Bs[0][c40+2][r0]=rb0.z; Bs[0][c40+3][r0]=rb0.w;
    Bs[0][c41+0][r1]=rb1.x; Bs[0][c41+1][r1]=rb1.y; Bs[0][c41+2][r1]=rb1.z; Bs[0][c41+3][r1]=rb1.w;
    __syncthreads();

    const int NT = Kd >> 4;
    for (int kt = 0; kt < NT; kt++) {
        const int cur = kt & 1;
        if (kt + 1 < NT) {
            const int ko = (kt + 1) << 4;
            ra0 = *(const float4*)(Ap0 + ko);
            ra1 = *(const float4*)(Ap1 + ko);
            rb0 = *(const float4*)(Bp0 + ko);
            rb1 = *(const float4*)(Bp1 + ko);
        }
#pragma unroll
        for (int kk = 0; kk < 16; kk++) {
            float a[8], b[8];
            *(float4*)&a[0] = *(const float4*)&As[cur][kk][ty*8];
            *(float4*)&a[4] = *(const float4*)&As[cur][kk][ty*8+4];
            *(float4*)&b[0] = *(const float4*)&Bs[cur][kk][tx*8];
            *(float4*)&b[4] = *(const float4*)&Bs[cur][kk][tx*8+4];
#pragma unroll
            for (int i = 0; i < 8; i++)
#pragma unroll
                for (int j = 0; j < 8; j++)
                    acc[i][j] = fmaf(a[i], b[j], acc[i][j]);
        }
        if (kt + 1 < NT) {
            const int nxt = cur ^ 1;
            As[nxt][c40+0][r0]=ra0.x; As[nxt][c40+1][r0]=ra0.y; As[nxt][c40+2][r0]=ra0.z; As[nxt][c40+3][r0]=ra0.w;
            As[nxt][c41+0][r1]=ra1.x; As[nxt][c41+1][r1]=ra1.y; As[nxt][c41+2][r1]=ra1.z; As[nxt][c41+3][r1]=ra1.w;
            Bs[nxt][c40+0][r0]=rb0.x; Bs[nxt][c40+1][r0]=rb0.y; Bs[nxt][c40+2][r0]=rb0.z; Bs[nxt][c40+3][r0]=rb0.w;
            Bs[nxt][c41+0][r1]=rb1.x; Bs[nxt][c41+1][r1]=rb1.y; Bs[nxt][c41+2][r1]=rb1.z; Bs[nxt][c41+3][r1]=rb1.w;
        }
        __syncthreads();
    }
#pragma unroll
    for (int i = 0; i < 8; i++) {
        int row = bm + ty*8 + i;
        float* cp = Cm + (size_t)row*N + bn + tx*8;
        float4 q0 = make_float4(acc[i][0], acc[i][1], acc[i][2], acc[i][3]);
        float4 q1 = make_float4(acc[i][4], acc[i][5], acc[i][6], acc[i][7]);
        if (resid) {
            const float* rp = resid + (size_t)row*N + bn + tx*8;
            float4 s0 = *(const float4*)&rp[0];
            float4 s1 = *(const float4*)&rp[4];
            q0.x += s0.x; q0.y += s0.y; q0.z += s0.z; q0.w += s0.w;
            q1.x += s1.x; q1.y += s1.y; q1.z += s1.z; q1.w += s1.w;
        }
        *(float4*)&cp[0] = q0;
        *(float4*)&cp[4] = q1;
    }
}

// ---------------- RoPE (in-place on q and k halves of g_qkv) ----------------
__global__ __launch_bounds__(256) void rope_kernel(
    const float* __restrict__ cosb, const float* __restrict__ sinb)
{
    const int NQ = BTn * Hn * 32;                    // 2^21 pairs per tensor
    int idx = blockIdx.x * 256 + threadIdx.x;        // 0 .. 2*NQ-1
    float* buf = g_qkv + (idx >= NQ ? (size_t)BTn * Cn : 0);
    int i  = idx & (NQ - 1);
    int d  = i & 31;
    int bh = i >> 5;                                  // (b*T + t)*H + h
    int t  = (bh >> 4) & (Tn - 1);
    size_t base = (size_t)bh * 64;
    float x1 = buf[base + d];
    float x2 = buf[base + d + 32];
    float c1 = cosb[t*64 + d],      s1 = sinb[t*64 + d];
    float c2 = cosb[t*64 + d + 32], s2 = sinb[t*64 + d + 32];
    buf[base + d]      = x1 * c1 - x2 * s1;
    buf[base + d + 32] = x2 * c2 + x1 * s2;
}

// ---------------- causal flash attention, fp32 ----------------
// grid (T/128, B*H), 128 threads; each thread owns one q row (q,O in regs).
__global__ __launch_bounds__(128) void attn_kernel(
    const float* __restrict__ q, const float* __restrict__ k,
    const float* __restrict__ v, float* __restrict__ y)
{
    __shared__ float Ks[64][64];
    __shared__ float Vs[64][64];
    const int tid = threadIdx.x;
    const int bh = blockIdx.y;
    const int b = bh >> 4;
    const int h = bh & 15;
    const int qi = blockIdx.x * 128 + tid;
    const size_t qoff = (((size_t)(b*Tn + qi))*Hn + h) * Dn;

    float qr[64];
#pragma unroll
    for (int i = 0; i < 16; i++) {
        float4 t4 = ((const float4*)(q + qoff))[i];
        qr[4*i+0] = t4.x * 0.125f; qr[4*i+1] = t4.y * 0.125f;
        qr[4*i+2] = t4.z * 0.125f; qr[4*i+3] = t4.w * 0.125f;
    }
    float o[64];
#pragma unroll
    for (int d = 0; d < 64; d++) o[d] = 0.f;
    float m = -INFINITY, l = 0.f;

    const int kt_end = (blockIdx.x * 128 + 127) >> 6;       // inclusive
    for (int kt = 0; kt <= kt_end; kt++) {
#pragma unroll
        for (int i = 0; i < 8; i++) {
            int idx = tid + i*128;                           // 1024 float4s per tile pair
            int r = idx >> 4;
            int c = (idx & 15) << 2;
            size_t off = (((size_t)(b*Tn + kt*64 + r))*Hn + h)*Dn + c;
            *(float4*)&Ks[r][c] = *(const float4*)&k[off];
            *(float4*)&Vs[r][c] = *(const float4*)&v[off];
        }
        __syncthreads();
        const int jmax = qi - kt*64;
#pragma unroll 1
        for (int jc = 0; jc < 64; jc += 8) {
            float s[8];
#pragma unroll
            for (int u = 0; u < 8; u++) {
                const float4* kp = (const float4*)Ks[jc + u];
                float a0 = 0.f, a1 = 0.f, a2 = 0.f, a3 = 0.f;
#pragma unroll
                for (int d4 = 0; d4 < 16; d4++) {
                    float4 kv = kp[d4];
                    a0 = fmaf(qr[4*d4+0], kv.x, a0);
                    a1 = fmaf(qr[4*d4+1], kv.y, a1);
                    a2 = fmaf(qr[4*d4+2], kv.z, a2);
                    a3 = fmaf(qr[4*d4+3], kv.w, a3);
                }
                float sv = (a0 + a1) + (a2 + a3);
                s[u] = (jc + u <= jmax) ? sv : -INFINITY;
            }
            float cm = s[0];
#pragma unroll
            for (int u = 1; u < 8; u++) cm = fmaxf(cm, s[u]);
            float mnew = fmaxf(m, cm);
            float scl = __expf(m - mnew);                    // exp(-inf)=0 on first chunk
            float p[8]; float psum = 0.f;
#pragma unroll
            for (int u = 0; u < 8; u++) { p[u] = __expf(s[u] - mnew); psum += p[u]; }
            l = l * scl + psum;
            m = mnew;
#pragma unroll
            for (int d4 = 0; d4 < 16; d4++) {
                float4 a4 = make_float4(o[4*d4+0]*scl, o[4*d4+1]*scl,
                                        o[4*d4+2]*scl, o[4*d4+3]*scl);
#pragma unroll
                for (int u = 0; u < 8; u++) {
                    float4 vv = ((const float4*)Vs[jc + u])[d4];
                    a4.x = fmaf(p[u], vv.x, a4.x);
                    a4.y = fmaf(p[u], vv.y, a4.y);
                    a4.z = fmaf(p[u], vv.z, a4.z);
                    a4.w = fmaf(p[u], vv.w, a4.w);
                }
                o[4*d4+0] = a4.x; o[4*d4+1] = a4.y; o[4*d4+2] = a4.z; o[4*d4+3] = a4.w;
            }
        }
        __syncthreads();
    }
    const float inv = 1.f / l;
    float* yp = y + qoff;
#pragma unroll
    for (int i = 0; i < 16; i++)
        ((float4*)yp)[i] = make_float4(o[4*i]*inv, o[4*i+1]*inv, o[4*i+2]*inv, o[4*i+3]*inv);
}

// ---------------- router: logits, top-2, softmax, scatter into expert lists ----------------
__global__ __launch_bounds__(256) void router_kernel(
    const float* __restrict__ hn, const float* __restrict__ rw)
{
    const int t = blockIdx.x;
    const int tid = threadIdx.x;
    const int lane = tid & 31, w = tid >> 5;
    __shared__ float logits[8];
    const float* xp = hn + (size_t)t * Cn;
    const float* wp = rw + (size_t)w * Cn;
    float s = 0.f;
    for (int c = lane; c < Cn; c += 32) s = fmaf(xp[c], wp[c], s);
#pragma unroll
    for (int off = 16; off > 0; off >>= 1) s += __shfl_xor_sync(0xffffffffu, s, off);
    if (lane == 0) logits[w] = s;
    __syncthreads();
    if (tid == 0) {
        float l0 = logits[0]; int e0 = 0;
#pragma unroll
        for (int e = 1; e < 8; e++) if (logits[e] > l0) { l0 = logits[e]; e0 = e; }
        float l1 = -INFINITY; int e1 = 0;
#pragma unroll
        for (int e = 0; e < 8; e++) if (e != e0 && logits[e] > l1) { l1 = logits[e]; e1 = e; }
        float g0 = 1.f / (1.f + __expf(l1 - l0));
        float g1 = 1.f - g0;
        int p0 = atomicAdd(&g_counts[e0], 1);
        g_tok[e0*4096 + p0] = t; g_gate[e0*4096 + p0] = g0;
        int p1 = atomicAdd(&g_counts[e1], 1);
        g_tok[e1*4096 + p1] = t; g_gate[e1*4096 + p1] = g1;
    }
}

// ---------------- MoE GEMM1: G = silu(X@w1^T) * (X@w3^T), gathered rows ----------------
// 128x64 tile (dual B), 256 threads, 8x4 per thread per matrix, double buffered.
__global__ __launch_bounds__(256) void moe_gemm1(
    const float* __restrict__ w1, const float* __restrict__ w3)
{
    const int e = blockIdx.z;
    const int cnt = g_counts[e];
    const int bm = blockIdx.y * 128;
    if (bm >= cnt) return;
    const int bn = blockIdx.x * 64;
    __shared__ float As[2][16][128];
    __shared__ float B1s[2][16][64];
    __shared__ float B3s[2][16][64];
    __shared__ int rowtok[128];
    const int tid = threadIdx.x;
    if (tid < 128) {
        int r = bm + tid;
        rowtok[tid] = g_tok[e*4096 + ((r < cnt) ? r : 0)];
    }
    __syncthreads();
    const float* W1 = w1 + (size_t)e * HDn * Cn;
    const float* W3 = w3 + (size_t)e * HDn * Cn;
    const int tx = tid & 15, ty = tid >> 4;

    const int r0 = tid >> 2,         c40 = (tid & 3) << 2;
    const int r1 = (tid + 256) >> 2;
    const float* Ap0 = &g_h[(size_t)rowtok[r0]*Cn + c40];
    const float* Ap1 = &g_h[(size_t)rowtok[r1]*Cn + c40];
    const float* B1p = &W1[(size_t)(bn + r0)*Cn + c40];    // r0 covers 0..63 only when tid<256 -> r0 in 0..63? (tid>>2 max 63) yes
    const float* B3p = &W3[(size_t)(bn + r0)*Cn + c40];

    float4 ra0, ra1, rb1, rb3;
    float acc1[8][4], acc3[8][4];
#pragma unroll
    for (int i = 0; i < 8; i++)
#pragma unroll
        for (int j = 0; j < 4; j++) { acc1[i][j] = 0.f; acc3[i][j] = 0.f; }

    // prologue
    ra0 = *(const float4*)(Ap0);
    ra1 = *(const float4*)(Ap1);
    rb1 = *(const float4*)(B1p);
    rb3 = *(const float4*)(B3p);
    As[0][c40+0][r0]=ra0.x; As[0][c40+1][r0]=ra0.y; As[0][c40+2][r0]=ra0.z; As[0][c40+3][r0]=ra0.w;
    As[0][c40+0][r1]=ra1.x; As[0][c40+1][r1]=ra1.y; As[0][c40+2][r1]=ra1.z; As[0][c40+3][r1]=ra1.w;
    B1s[0][c40+0][r0]=rb1.x; B1s[0][c40+1][r0]=rb1.y; B1s[0][c40+2][r0]=rb1.z; B1s[0][c40+3][r0]=rb1.w;
    B3s[0][c40+0][r0]=rb3.x; B3s[0][c40+1][r0]=rb3.y; B3s[0][c40+2][r0]=rb3.z; B3s[0][c40+3][r0]=rb3.w;
    __syncthreads();

    const int NT = Cn >> 4;
    for (int kt = 0; kt < NT; kt++) {
        const int cur = kt & 1;
        if (kt + 1 < NT) {
            const int ko = (kt + 1) << 4;
            ra0 = *(const float4*)(Ap0 + ko);
            ra1 = *(const float4*)(Ap1 + ko);
            rb1 = *(const float4*)(B1p + ko);
            rb3 = *(const float4*)(B3p + ko);
        }
#pragma unroll
        for (int kk = 0; kk < 16; kk++) {
            float a[8], b1[4], b3[4];
            *(float4*)&a[0]  = *(const float4*)&As[cur][kk][ty*8];
            *(float4*)&a[4]  = *(const float4*)&As[cur][kk][ty*8+4];
            *(float4*)&b1[0] = *(const float4*)&B1s[cur][kk][tx*4];
            *(float4*)&b3[0] = *(const float4*)&B3s[cur][kk][tx*4];
#pragma unroll
            for (int i = 0; i < 8; i++)
#pragma unroll
                for (int j = 0; j < 4; j++) {
                    acc1[i][j] = fmaf(a[i], b1[j], acc1[i][j]);
                    acc3[i][j] = fmaf(a[i], b3[j], acc3[i][j]);
                }
        }
        if (kt + 1 < NT) {
            const int nxt = cur ^ 1;
            As[nxt][c40+0][r0]=ra0.x; As[nxt][c40+1][r0]=ra0.y; As[nxt][c40+2][r0]=ra0.z; As[nxt][c40+3][r0]=ra0.w;
            As[nxt][c40+0][r1]=ra1.x; As[nxt][c40+1][r1]=ra1.y; As[nxt][c40+2][r1]=ra1.z; As[nxt][c40+3][r1]=ra1.w;
            B1s[nxt][c40+0][r0]=rb1.x; B1s[nxt][c40+1][r0]=rb1.y; B1s[nxt][c40+2][r0]=rb1.z; B1s[nxt][c40+3][r0]=rb1.w;
            B3s[nxt][c40+0][r0]=rb3.x; B3s[nxt][c40+1][r0]=rb3.y; B3s[nxt][c40+2][r0]=rb3.z; B3s[nxt][c40+3][r0]=rb3.w;
        }
        __syncthreads();
    }
#pragma unroll
    for (int i = 0; i < 8; i++) {
        int row = bm + ty*8 + i;
        if (row < cnt) {
            float gv[4];
#pragma unroll
            for (int j = 0; j < 4; j++) {
                float a = acc1[i][j];
                float sig = 1.f / (1.f + __expf(-a));
                gv[j] = a * sig * acc3[i][j];
            }
            *(float4*)&g_g[((size_t)e*4096 + row)*HDn + bn + tx*4] =
                make_float4(gv[0], gv[1], gv[2], gv[3]);
        }
    }
}

// ---------------- MoE GEMM2: Y = G @ w2^T, scatter-add gate*Y into g_moe ----------------
__global__ __launch_bounds__(256) void moe_gemm2(const float* __restrict__ w2)
{
    const int e = blockIdx.z;
    const int cnt = g_counts[e];
    const int bm = blockIdx.y * 128;
    if (bm >= cnt) return;
    const int bn = blockIdx.x * 128;
    __shared__ float As[2][16][128];
    __shared__ float Bs[2][16][128];
    const float* Am = g_g + (size_t)e * 4096 * HDn;
    const float* Bm = w2 + (size_t)e * Cn * HDn;
    const int tid = threadIdx.x;
    const int tx = tid & 15, ty = tid >> 4;

    const int r0 = tid >> 2,         c40 = (tid & 3) << 2;
    const int r1 = (tid + 256) >> 2;
    const float* Ap0 = &Am[(size_t)(bm + r0)*HDn + c40];
    const float* Ap1 = &Am[(size_t)(bm + r1)*HDn + c40];
    const float* Bp0 = &Bm[(size_t)(bn + r0)*HDn + c40];
    const float* Bp1 = &Bm[(size_t)(bn + r1)*HDn + c40];

    float4 ra0, ra1, rb0, rb1;
    float acc[8][8];
#pragma unroll
    for (int i = 0; i < 8; i++)
#pragma unroll
        for (int j = 0; j < 8; j++) acc[i][j] = 0.f;

    ra0 = *(const float4*)(Ap0);
    ra1 = *(const float4*)(Ap1);
    rb0 = *(const float4*)(Bp0);
    rb1 = *(const float4*)(Bp1);
    As[0][c40+0][r0]=ra0.x; As[0][c40+1][r0]=ra0.y; As[0][c40+2][r0]=ra0.z; As[0][c40+3][r0]=ra0.w;
    As[0][c40+0][r1]=ra1.x; As[0][c40+1][r1]=ra1.y; As[0][c40+2][r1]=ra1.z; As[0][c40+3][r1]=ra1.w;
    Bs[0][c40+0][r0]=rb0.x; Bs[0][c40+1][r0]=rb0.y; Bs[0][c40+2][r0]=rb0.z; Bs[0][c40+3][r0]=rb0.w;
    Bs[0][c40+0][r1]=rb1.x; Bs[0][c40+1][r1]=rb1.y; Bs[0][c40+2][r1]=rb1.z; Bs[0][c40+3][r1]=rb1.w;
    __syncthreads();

    const int NT = HDn >> 4;
    for (int kt = 0; kt < NT; kt++) {
        const int cur = kt & 1;
        if (kt + 1 < NT) {
            const int ko = (kt + 1) << 4;
            ra0 = *(const float4*)(Ap0 + ko);
            ra1 = *(const float4*)(Ap1 + ko);
            rb0 = *(const float4*)(Bp0 + ko);
            rb1 = *(const float4*)(Bp1 + ko);
        }
#pragma unroll
        for (int kk = 0; kk < 16; kk++) {
            float a[8], b[8];
            *(float4*)&a[0] = *(const float4*)&As[cur][kk][ty*8];
            *(float4*)&a[4] = *(const float4*)&As[cur][kk][ty*8+4];
            *(float4*)&b[0] = *(const float4*)&Bs[cur][kk][tx*8];
            *(float4*)&b[4] = *(const float4*)&Bs[cur][kk][tx*8+4];
#pragma unroll
            for (int i = 0; i < 8; i++)
#pragma unroll
                for (int j = 0; j < 8; j++)
                    acc[i][j] = fmaf(a[i], b[j], acc[i][j]);
        }
        if (kt + 1 < NT) {
            const int nxt = cur ^ 1;
            As[nxt][c40+0][r0]=ra0.x; As[nxt][c40+1][r0]=ra0.y; As[nxt][c40+2][r0]=ra0.z; As[nxt][c40+3][r0]=ra0.w;
            As[nxt][c40+0][r1]=ra1.x; As[nxt][c40+1][r1]=ra1.y; As[nxt][c40+2][r1]=ra1.z; As[nxt][c40+3][r1]=ra1.w;
            Bs[nxt][c40+0][r0]=rb0.x; Bs[nxt][c40+1][r0]=rb0.y; Bs[nxt][c40+2][r0]=rb0.z; Bs[nxt][c40+3][r0]=rb0.w;
            Bs[nxt][c40+0][r1]=rb1.x; Bs[nxt][c40+1][r1]=rb1.y; Bs[nxt][c40+2][r1]=rb1.z; Bs[nxt][c40+3][r1]=rb1.w;
        }
        __syncthreads();
    }
#pragma unroll
    for (int i = 0; i < 8; i++) {
        int row = bm + ty*8 + i;
        if (row < cnt) {
            int tok = g_tok[e*4096 + row];
            float gt = g_gate[e*4096 + row];
            float* mp = &g_moe[(size_t)tok*Cn + bn + tx*8];
#pragma unroll
            for (int j = 0; j < 8; j++) atomicAdd(&mp[j], gt * acc[i][j]);
        }
    }
}

// ---------------- final: out += moe ----------------
__global__ void final_add(float* __restrict__ out) {
    int i = blockIdx.x * 256 + threadIdx.x;
    float4 a = ((float4*)out)[i];
    float4 bb = ((const float4*)g_moe)[i];
    a.x += bb.x; a.y += bb.y; a.z += bb.z; a.w += bb.w;
    ((float4*)out)[i] = a;
}

// ---------------- launch ----------------
extern "C" void kernel_launch(void* const* d_in, const int* in_sizes, int n_in,
                              void* d_out, int out_size)
{
    const float* x        = (const float*)d_in[0];
    const float* rope_cos = (const float*)d_in[1];
    const float* rope_sin = (const float*)d_in[2];
    const float* attn_nw  = (const float*)d_in[3];
    const float* q_w      = (const float*)d_in[4];
    const float* k_w      = (const float*)d_in[5];
    const float* v_w      = (const float*)d_in[6];
    const float* o_w      = (const float*)d_in[7];
    const float* ffn_nw   = (const float*)d_in[8];
    const float* router_w = (const float*)d_in[9];
    const float* w1       = (const float*)d_in[10];
    const float* w2       = (const float*)d_in[11];
    const float* w3       = (const float*)d_in[12];
    float* out = (float*)d_out;

    float *p_h, *p_qkv, *p_y;
    cudaGetSymbolAddress((void**)&p_h,   g_h);
    cudaGetSymbolAddress((void**)&p_qkv, g_qkv);
    cudaGetSymbolAddress((void**)&p_y,   g_y);

    // 1. zero moe accumulator + expert counters
    zero_kernel<<<(BTn*Cn/4)/256, 256>>>();
    // 2. attention rmsnorm
    rmsnorm_kernel<<<BTn, 256>>>(x, attn_nw, p_h);
    // 3. fused QKV projection (z selects weight/output)
    gemm_big<<<dim3(Cn/128, BTn/128, 3), 256>>>(p_h, q_w, k_w, v_w,
                                                p_qkv, (size_t)BTn*Cn, nullptr, Cn, Cn);
    // 4. RoPE on q and k
    rope_kernel<<<(2*BTn*Hn*32)/256, 256>>>(rope_cos, rope_sin);
    // 5. causal flash attention
    attn_kernel<<<dim3(Tn/128, Bn*Hn), 128>>>(p_qkv, p_qkv + (size_t)BTn*Cn,
                                              p_qkv + 2*(size_t)BTn*Cn, p_y);
    // 6. O projection + residual -> d_out
    gemm_big<<<dim3(Cn/128, BTn/128, 1), 256>>>(p_y, o_w, o_w, o_w,
                                                out, 0, x, Cn, Cn);
    // 7. ffn rmsnorm (reuse g_h)
    rmsnorm_kernel<<<BTn, 256>>>(out, ffn_nw, p_h);
    // 8. router: top-2 + scatter
    router_kernel<<<BTn, 256>>>(p_h, router_w);
    // 9. expert up-projections (fused w1/w3 + silu gate)
    moe_gemm1<<<dim3(HDn/64, 4096/128, En), 256>>>(w1, w3);
    // 10. expert down-projection + gated scatter-add
    moe_gemm2<<<dim3(Cn/128, 4096/128, En), 256>>>(w2);
    // 11. out += moe
    final_add<<<(BTn*Cn/4)/256, 256>>>(out);
}

// round 5
// speedup vs baseline: 1.7897x; 1.7897x over previous
#include <cuda_runtime.h>
#include <math.h>
#include <stdint.h>

#define Bn  2
#define Tn  2048
#define Cn  1024
#define Hn  16
#define Dn  64
#define En  8
#define HDn 1536
#define BTn (Bn*Tn)          // 4096 tokens

// ---------------- scratch (device globals; no allocations allowed) ----------------
__device__ float g_h[BTn*Cn];                       // rmsnorm output (reused for ffn norm)
__device__ float g_qkv[3*BTn*Cn];                   // q | k | v, each [BT][H*D]
__device__ float g_y[BTn*Cn];                       // attention output
__device__ float g_moe[BTn*Cn];                     // MoE accumulation
__device__ float g_g[(size_t)En*4096*HDn];          // gated hidden per expert row block
__device__ int   g_tok[En*4096];
__device__ float g_gate[En*4096];
__device__ int   g_counts[En];

// ---------------- tf32 helpers ----------------
__device__ __forceinline__ uint32_t f2tf32(float x) {
    uint32_t r; asm("cvt.rna.tf32.f32 %0, %1;" : "=r"(r) : "f"(x)); return r;
}
__device__ __forceinline__ void mma8(float* c, uint32_t a0, uint32_t a1, uint32_t a2, uint32_t a3,
                                     uint32_t b0, uint32_t b1) {
    asm volatile("mma.sync.aligned.m16n8k8.row.col.f32.tf32.tf32.f32 "
                 "{%0,%1,%2,%3}, {%4,%5,%6,%7}, {%8,%9}, {%0,%1,%2,%3};\n"
                 : "+f"(c[0]), "+f"(c[1]), "+f"(c[2]), "+f"(c[3])
                 : "r"(a0), "r"(a1), "r"(a2), "r"(a3), "r"(b0), "r"(b1));
}
#define SA 138   // smem row pad (mod 32 == 10): conflict-free STS, near-clean LDS
#define SB 74

#define STS4(buf, kc, row, v) do { \
    buf[(kc)+0][row] = f2tf32((v).x); buf[(kc)+1][row] = f2tf32((v).y); \
    buf[(kc)+2][row] = f2tf32((v).z); buf[(kc)+3][row] = f2tf32((v).w); } while (0)

// ---------------- zero scratch ----------------
__global__ void zero_kernel() {
    int i = blockIdx.x * 256 + threadIdx.x;          // BT*C/4 threads
    ((float4*)g_moe)[i] = make_float4(0.f, 0.f, 0.f, 0.f);
    if (i < En) g_counts[i] = 0;
}

// ---------------- rmsnorm: one block per token ----------------
__global__ __launch_bounds__(256) void rmsnorm_kernel(
    const float* __restrict__ x, const float* __restrict__ w, float* __restrict__ out)
{
    const int t = blockIdx.x;
    const int tid = threadIdx.x;
    const float* xp = x + (size_t)t * Cn;
    float v0 = xp[tid], v1 = xp[tid+256], v2 = xp[tid+512], v3 = xp[tid+768];
    float s = v0*v0 + v1*v1 + v2*v2 + v3*v3;
#pragma unroll
    for (int off = 16; off > 0; off >>= 1) s += __shfl_xor_sync(0xffffffffu, s, off);
    __shared__ float ws[8];
    if ((tid & 31) == 0) ws[tid >> 5] = s;
    __syncthreads();
    float tot = 0.f;
#pragma unroll
    for (int i = 0; i < 8; i++) tot += ws[i];
    const float r = rsqrtf(tot * (1.f/Cn) + 1e-6f);
    float* op = out + (size_t)t * Cn;
    op[tid]     = w[tid]     * v0 * r;
    op[tid+256] = w[tid+256] * v1 * r;
    op[tid+512] = w[tid+512] * v2 * r;
    op[tid+768] = w[tid+768] * v3 * r;
}

// ---------------- tf32 tensor-core GEMM: C[M,N]=A[M,K]@B[N,K]^T (+resid) ----------
// 128x128 block, 8 warps (2m x 4n), warp tile 64x32, BK=16, double buffered.
__global__ __launch_bounds__(256, 2) void gemm_tf32(
    const float* __restrict__ A,
    const float* __restrict__ B0, const float* __restrict__ B1, const float* __restrict__ B2,
    float* Cbase, size_t cstride,
    const float* __restrict__ resid,
    int Kd, int N)
{
    const int z = blockIdx.z;
    const float* Bmat = (z == 0) ? B0 : (z == 1) ? B1 : B2;
    float* Cm = Cbase + (size_t)z * cstride;
    __shared__ uint32_t As[2][16][SA];
    __shared__ uint32_t Bs[2][16][SA];
    const int tid = threadIdx.x;
    const int bm = blockIdx.y * 128, bn = blockIdx.x * 128;
    const int w = tid >> 5, lane = tid & 31, grp = lane >> 2, tig = lane & 3;
    const int wm = (w & 1) * 64, wn = (w >> 1) * 32;

    const int r0 = tid >> 2, c40 = (tid & 3) << 2;
    const float* Ap0 = A    + (size_t)(bm + r0)      * Kd + c40;
    const float* Ap1 = A    + (size_t)(bm + r0 + 64) * Kd + c40;
    const float* Bp0 = Bmat + (size_t)(bn + r0)      * Kd + c40;
    const float* Bp1 = Bmat + (size_t)(bn + r0 + 64) * Kd + c40;

    float acc[4][4][4];
#pragma unroll
    for (int mt = 0; mt < 4; mt++)
#pragma unroll
        for (int nt = 0; nt < 4; nt++)
#pragma unroll
            for (int i = 0; i < 4; i++) acc[mt][nt][i] = 0.f;

    float4 ra0 = *(const float4*)Ap0, ra1 = *(const float4*)Ap1;
    float4 rb0 = *(const float4*)Bp0, rb1 = *(const float4*)Bp1;
    STS4(As[0], c40, r0,      ra0); STS4(As[0], c40, r0 + 64, ra1);
    STS4(Bs[0], c40, r0,      rb0); STS4(Bs[0], c40, r0 + 64, rb1);
    __syncthreads();

    const int NT = Kd >> 4;
    for (int kt = 0; kt < NT; kt++) {
        const int cur = kt & 1;
        if (kt + 1 < NT) {
            const int ko = (kt + 1) << 4;
            ra0 = *(const float4*)(Ap0 + ko); ra1 = *(const float4*)(Ap1 + ko);
            rb0 = *(const float4*)(Bp0 + ko); rb1 = *(const float4*)(Bp1 + ko);
        }
#pragma unroll
        for (int kb = 0; kb < 16; kb += 8) {
            uint32_t bf[4][2];
#pragma unroll
            for (int nt = 0; nt < 4; nt++) {
                const int n0 = wn + nt*8 + grp;
                bf[nt][0] = Bs[cur][kb + tig][n0];
                bf[nt][1] = Bs[cur][kb + tig + 4][n0];
            }
#pragma unroll
            for (int mt = 0; mt < 4; mt++) {
                const int m0 = wm + mt*16 + grp;
                uint32_t a0 = As[cur][kb + tig][m0];
                uint32_t a1 = As[cur][kb + tig][m0 + 8];
                uint32_t a2 = As[cur][kb + tig + 4][m0];
                uint32_t a3 = As[cur][kb + tig + 4][m0 + 8];
#pragma unroll
                for (int nt = 0; nt < 4; nt++)
                    mma8(acc[mt][nt], a0, a1, a2, a3, bf[nt][0], bf[nt][1]);
            }
        }
        if (kt + 1 < NT) {
            const int nx = cur ^ 1;
            STS4(As[nx], c40, r0,      ra0); STS4(As[nx], c40, r0 + 64, ra1);
            STS4(Bs[nx], c40, r0,      rb0); STS4(Bs[nx], c40, r0 + 64, rb1);
        }
        __syncthreads();
    }
#pragma unroll
    for (int mt = 0; mt < 4; mt++) {
        const int rg = bm + wm + mt*16 + grp;
#pragma unroll
        for (int nt = 0; nt < 4; nt++) {
            const int col = bn + wn + nt*8 + 2*tig;
            float2 v0 = make_float2(acc[mt][nt][0], acc[mt][nt][1]);
            float2 v1 = make_float2(acc[mt][nt][2], acc[mt][nt][3]);
            if (resid) {
                float2 s0 = *(const float2*)&resid[(size_t)rg*N + col];
                float2 s1 = *(const float2*)&resid[(size_t)(rg+8)*N + col];
                v0.x += s0.x; v0.y += s0.y; v1.x += s1.x; v1.y += s1.y;
            }
            *(float2*)&Cm[(size_t)rg*N + col]     = v0;
            *(float2*)&Cm[(size_t)(rg+8)*N + col] = v1;
        }
    }
}

// ---------------- RoPE (in-place on q and k halves of g_qkv) ----------------
__global__ __launch_bounds__(256) void rope_kernel(
    const float* __restrict__ cosb, const float* __restrict__ sinb)
{
    const int NQ = BTn * Hn * 32;                    // 2^21 pairs per tensor
    int idx = blockIdx.x * 256 + threadIdx.x;        // 0 .. 2*NQ-1
    float* buf = g_qkv + (idx >= NQ ? (size_t)BTn * Cn : 0);
    int i  = idx & (NQ - 1);
    int d  = i & 31;
    int bh = i >> 5;                                  // (b*T + t)*H + h
    int t  = (bh >> 4) & (Tn - 1);
    size_t base = (size_t)bh * 64;
    float x1 = buf[base + d];
    float x2 = buf[base + d + 32];
    float c1 = cosb[t*64 + d],      s1 = sinb[t*64 + d];
    float c2 = cosb[t*64 + d + 32], s2 = sinb[t*64 + d + 32];
    buf[base + d]      = x1 * c1 - x2 * s1;
    buf[base + d + 32] = x2 * c2 + x1 * s2;
}

// ---------------- causal flash attention, fp32 ----------------
__global__ __launch_bounds__(128) void attn_kernel(
    const float* __restrict__ q, const float* __restrict__ k,
    const float* __restrict__ v, float* __restrict__ y)
{
    __shared__ float Ks[64][64];
    __shared__ float Vs[64][64];
    const int tid = threadIdx.x;
    const int bh = blockIdx.y;
    const int b = bh >> 4;
    const int h = bh & 15;
    const int qi = blockIdx.x * 128 + tid;
    const size_t qoff = (((size_t)(b*Tn + qi))*Hn + h) * Dn;

    float qr[64];
#pragma unroll
    for (int i = 0; i < 16; i++) {
        float4 t4 = ((const float4*)(q + qoff))[i];
        qr[4*i+0] = t4.x * 0.125f; qr[4*i+1] = t4.y * 0.125f;
        qr[4*i+2] = t4.z * 0.125f; qr[4*i+3] = t4.w * 0.125f;
    }
    float o[64];
#pragma unroll
    for (int d = 0; d < 64; d++) o[d] = 0.f;
    float m = -INFINITY, l = 0.f;

    const int kt_end = (blockIdx.x * 128 + 127) >> 6;       // inclusive
    for (int kt = 0; kt <= kt_end; kt++) {
#pragma unroll
        for (int i = 0; i < 8; i++) {
            int idx = tid + i*128;
            int r = idx >> 4;
            int c = (idx & 15) << 2;
            size_t off = (((size_t)(b*Tn + kt*64 + r))*Hn + h)*Dn + c;
            *(float4*)&Ks[r][c] = *(const float4*)&k[off];
            *(float4*)&Vs[r][c] = *(const float4*)&v[off];
        }
        __syncthreads();
        const int jmax = qi - kt*64;
#pragma unroll 1
        for (int jc = 0; jc < 64; jc += 8) {
            float s[8];
#pragma unroll
            for (int u = 0; u < 8; u++) {
                const float4* kp = (const float4*)Ks[jc + u];
                float a0 = 0.f, a1 = 0.f, a2 = 0.f, a3 = 0.f;
#pragma unroll
                for (int d4 = 0; d4 < 16; d4++) {
                    float4 kv = kp[d4];
                    a0 = fmaf(qr[4*d4+0], kv.x, a0);
                    a1 = fmaf(qr[4*d4+1], kv.y, a1);
                    a2 = fmaf(qr[4*d4+2], kv.z, a2);
                    a3 = fmaf(qr[4*d4+3], kv.w, a3);
                }
                float sv = (a0 + a1) + (a2 + a3);
                s[u] = (jc + u <= jmax) ? sv : -INFINITY;
            }
            float cm = s[0];
#pragma unroll
            for (int u = 1; u < 8; u++) cm = fmaxf(cm, s[u]);
            float mnew = fmaxf(m, cm);
            float scl = __expf(m - mnew);
            float p[8]; float psum = 0.f;
#pragma unroll
            for (int u = 0; u < 8; u++) { p[u] = __expf(s[u] - mnew); psum += p[u]; }
            l = l * scl + psum;
            m = mnew;
#pragma unroll
            for (int d4 = 0; d4 < 16; d4++) {
                float4 a4 = make_float4(o[4*d4+0]*scl, o[4*d4+1]*scl,
                                        o[4*d4+2]*scl, o[4*d4+3]*scl);
#pragma unroll
                for (int u = 0; u < 8; u++) {
                    float4 vv = ((const float4*)Vs[jc + u])[d4];
                    a4.x = fmaf(p[u], vv.x, a4.x);
                    a4.y = fmaf(p[u], vv.y, a4.y);
                    a4.z = fmaf(p[u], vv.z, a4.z);
                    a4.w = fmaf(p[u], vv.w, a4.w);
                }
                o[4*d4+0] = a4.x; o[4*d4+1] = a4.y; o[4*d4+2] = a4.z; o[4*d4+3] = a4.w;
            }
        }
        __syncthreads();
    }
    const float inv = 1.f / l;
    float* yp = y + qoff;
#pragma unroll
    for (int i = 0; i < 16; i++)
        ((float4*)yp)[i] = make_float4(o[4*i]*inv, o[4*i+1]*inv, o[4*i+2]*inv, o[4*i+3]*inv);
}

// ---------------- router ----------------
__global__ __launch_bounds__(256) void router_kernel(
    const float* __restrict__ hn, const float* __restrict__ rw)
{
    const int t = blockIdx.x;
    const int tid = threadIdx.x;
    const int lane = tid & 31, w = tid >> 5;
    __shared__ float logits[8];
    const float* xp = hn + (size_t)t * Cn;
    const float* wp = rw + (size_t)w * Cn;
    float s = 0.f;
    for (int c = lane; c < Cn; c += 32) s = fmaf(xp[c], wp[c], s);
#pragma unroll
    for (int off = 16; off > 0; off >>= 1) s += __shfl_xor_sync(0xffffffffu, s, off);
    if (lane == 0) logits[w] = s;
    __syncthreads();
    if (tid == 0) {
        float l0 = logits[0]; int e0 = 0;
#pragma unroll
        for (int e = 1; e < 8; e++) if (logits[e] > l0) { l0 = logits[e]; e0 = e; }
        float l1 = -INFINITY; int e1 = 0;
#pragma unroll
        for (int e = 0; e < 8; e++) if (e != e0 && logits[e] > l1) { l1 = logits[e]; e1 = e; }
        float g0 = 1.f / (1.f + __expf(l1 - l0));
        float g1 = 1.f - g0;
        int p0 = atomicAdd(&g_counts[e0], 1);
        g_tok[e0*4096 + p0] = t; g_gate[e0*4096 + p0] = g0;
        int p1 = atomicAdd(&g_counts[e1], 1);
        g_tok[e1*4096 + p1] = t; g_gate[e1*4096 + p1] = g1;
    }
}

// ---------------- MoE GEMM1 (tf32): G = silu(X@w1^T)*(X@w3^T), gathered rows ----
// 128x64 block, 8 warps (4m x 2n), warp tile 32x32, dual accumulators.
__global__ __launch_bounds__(256, 2) void moe_gemm1_tf32(
    const float* __restrict__ w1, const float* __restrict__ w3)
{
    const int e = blockIdx.z;
    const int cnt = g_counts[e];
    const int bm = blockIdx.y * 128;
    if (bm >= cnt) return;
    const int bn = blockIdx.x * 64;
    __shared__ uint32_t As[2][16][SA];
    __shared__ uint32_t B1s[2][16][SB];
    __shared__ uint32_t B3s[2][16][SB];
    __shared__ int rowtok[128];
    const int tid = threadIdx.x;
    if (tid < 128) {
        int r = bm + tid;
        rowtok[tid] = g_tok[e*4096 + ((r < cnt) ? r : 0)];
    }
    __syncthreads();
    const float* W1 = w1 + (size_t)e * HDn * Cn;
    const float* W3 = w3 + (size_t)e * HDn * Cn;
    const int w = tid >> 5, lane = tid & 31, grp = lane >> 2, tig = lane & 3;
    const int wm = (w & 3) * 32, wn = (w >> 2) * 32;

    const int r0 = tid >> 2, c40 = (tid & 3) << 2;
    const float* Ap0 = g_h + (size_t)rowtok[r0]      * Cn + c40;
    const float* Ap1 = g_h + (size_t)rowtok[r0 + 64] * Cn + c40;
    const float* B1p = W1  + (size_t)(bn + r0) * Cn + c40;
    const float* B3p = W3  + (size_t)(bn + r0) * Cn + c40;

    float acc1[2][4][4], acc3[2][4][4];
#pragma unroll
    for (int mt = 0; mt < 2; mt++)
#pragma unroll
        for (int nt = 0; nt < 4; nt++)
#pragma unroll
            for (int i = 0; i < 4; i++) { acc1[mt][nt][i] = 0.f; acc3[mt][nt][i] = 0.f; }

    float4 ra0 = *(const float4*)Ap0, ra1 = *(const float4*)Ap1;
    float4 rb1 = *(const float4*)B1p, rb3 = *(const float4*)B3p;
    STS4(As[0], c40, r0, ra0); STS4(As[0], c40, r0 + 64, ra1);
    STS4(B1s[0], c40, r0, rb1); STS4(B3s[0], c40, r0, rb3);
    __syncthreads();

    const int NT = Cn >> 4;
    for (int kt = 0; kt < NT; kt++) {
        const int cur = kt & 1;
        if (kt + 1 < NT) {
            const int ko = (kt + 1) << 4;
            ra0 = *(const float4*)(Ap0 + ko); ra1 = *(const float4*)(Ap1 + ko);
            rb1 = *(const float4*)(B1p + ko); rb3 = *(const float4*)(B3p + ko);
        }
#pragma unroll
        for (int kb = 0; kb < 16; kb += 8) {
            uint32_t bf1[4][2], bf3[4][2];
#pragma unroll
            for (int nt = 0; nt < 4; nt++) {
                const int n0 = wn + nt*8 + grp;
                bf1[nt][0] = B1s[cur][kb + tig][n0];
                bf1[nt][1] = B1s[cur][kb + tig + 4][n0];
                bf3[nt][0] = B3s[cur][kb + tig][n0];
                bf3[nt][1] = B3s[cur][kb + tig + 4][n0];
            }
#pragma unroll
            for (int mt = 0; mt < 2; mt++) {
                const int m0 = wm + mt*16 + grp;
                uint32_t a0 = As[cur][kb + tig][m0];
                uint32_t a1 = As[cur][kb + tig][m0 + 8];
                uint32_t a2 = As[cur][kb + tig + 4][m0];
                uint32_t a3 = As[cur][kb + tig + 4][m0 + 8];
#pragma unroll
                for (int nt = 0; nt < 4; nt++) {
                    mma8(acc1[mt][nt], a0, a1, a2, a3, bf1[nt][0], bf1[nt][1]);
                    mma8(acc3[mt][nt], a0, a1, a2, a3, bf3[nt][0], bf3[nt][1]);
                }
            }
        }
        if (kt + 1 < NT) {
            const int nx = cur ^ 1;
            STS4(As[nx], c40, r0, ra0); STS4(As[nx], c40, r0 + 64, ra1);
            STS4(B1s[nx], c40, r0, rb1); STS4(B3s[nx], c40, r0, rb3);
        }
        __syncthreads();
    }
#pragma unroll
    for (int mt = 0; mt < 2; mt++) {
#pragma unroll
        for (int half = 0; half < 2; half++) {
            const int rl = wm + mt*16 + grp + half*8;
            if (bm + rl < cnt) {
                float* gp = &g_g[((size_t)e*4096 + bm + rl)*HDn + bn];
#pragma unroll
                for (int nt = 0; nt < 4; nt++) {
                    const int col = wn + nt*8 + 2*tig;
                    float u0 = acc1[mt][nt][2*half+0], v0 = acc3[mt][nt][2*half+0];
                    float u1 = acc1[mt][nt][2*half+1], v1 = acc3[mt][nt][2*half+1];
                    float g0 = u0 / (1.f + __expf(-u0)) * v0;
                    float g1 = u1 / (1.f + __expf(-u1)) * v1;
                    *(float2*)&gp[col] = make_float2(g0, g1);
                }
            }
        }
    }
}

// ---------------- MoE GEMM2 (tf32): Y = G @ w2^T, gated scatter-add -----------
__global__ __launch_bounds__(256, 2) void moe_gemm2_tf32(const float* __restrict__ w2)
{
    const int e = blockIdx.z;
    const int cnt = g_counts[e];
    const int bm = blockIdx.y * 128;
    if (bm >= cnt) return;
    const int bn = blockIdx.x * 128;
    __shared__ uint32_t As[2][16][SA];
    __shared__ uint32_t Bs[2][16][SA];
    const float* Am = g_g + (size_t)e * 4096 * HDn;
    const float* Bmat = w2 + (size_t)e * Cn * HDn;
    const int tid = threadIdx.x;
    const int w = tid >> 5, lane = tid & 31, grp = lane >> 2, tig = lane & 3;
    const int wm = (w & 1) * 64, wn = (w >> 1) * 32;

    const int r0 = tid >> 2, c40 = (tid & 3) << 2;
    const float* Ap0 = Am   + (size_t)(bm + r0)      * HDn + c40;
    const float* Ap1 = Am   + (size_t)(bm + r0 + 64) * HDn + c40;
    const float* Bp0 = Bmat + (size_t)(bn + r0)      * HDn + c40;
    const float* Bp1 = Bmat + (size_t)(bn + r0 + 64) * HDn + c40;

    float acc[4][4][4];
#pragma unroll
    for (int mt = 0; mt < 4; mt++)
#pragma unroll
        for (int nt = 0; nt < 4; nt++)
#pragma unroll
            for (int i = 0; i < 4; i++) acc[mt][nt][i] = 0.f;

    float4 ra0 = *(const float4*)Ap0, ra1 = *(const float4*)Ap1;
    float4 rb0 = *(const float4*)Bp0, rb1 = *(const float4*)Bp1;
    STS4(As[0], c40, r0, ra0); STS4(As[0], c40, r0 + 64, ra1);
    STS4(Bs[0], c40, r0, rb0); STS4(Bs[0], c40, r0 + 64, rb1);
    __syncthreads();

    const int NT = HDn >> 4;
    for (int kt = 0; kt < NT; kt++) {
        const int cur = kt & 1;
        if (kt + 1 < NT) {
            const int ko = (kt + 1) << 4;
            ra0 = *(const float4*)(Ap0 + ko); ra1 = *(const float4*)(Ap1 + ko);
            rb0 = *(const float4*)(Bp0 + ko); rb1 = *(const float4*)(Bp1 + ko);
        }
#pragma unroll
        for (int kb = 0; kb < 16; kb += 8) {
            uint32_t bf[4][2];
#pragma unroll
            for (int nt = 0; nt < 4; nt++) {
                const int n0 = wn + nt*8 + grp;
                bf[nt][0] = Bs[cur][kb + tig][n0];
                bf[nt][1] = Bs[cur][kb + tig + 4][n0];
            }
#pragma unroll
            for (int mt = 0; mt < 4; mt++) {
                const int m0 = wm + mt*16 + grp;
                uint32_t a0 = As[cur][kb + tig][m0];
                uint32_t a1 = As[cur][kb + tig][m0 + 8];
                uint32_t a2 = As[cur][kb + tig + 4][m0];
                uint32_t a3 = As[cur][kb + tig + 4][m0 + 8];
#pragma unroll
                for (int nt = 0; nt < 4; nt++)
                    mma8(acc[mt][nt], a0, a1, a2, a3, bf[nt][0], bf[nt][1]);
            }
        }
        if (kt + 1 < NT) {
            const int nx = cur ^ 1;
            STS4(As[nx], c40, r0, ra0); STS4(As[nx], c40, r0 + 64, ra1);
            STS4(Bs[nx], c40, r0, rb0); STS4(Bs[nx], c40, r0 + 64, rb1);
        }
        __syncthreads();
    }
#pragma unroll
    for (int mt = 0; mt < 4; mt++) {
#pragma unroll
        for (int half = 0; half < 2; half++) {
            const int rl = wm + mt*16 + grp + half*8;
            if (bm + rl < cnt) {
                const int tok = g_tok[e*4096 + bm + rl];
                const float gt = g_gate[e*4096 + bm + rl];
                float* mp = &g_moe[(size_t)tok*Cn + bn];
#pragma unroll
                for (int nt = 0; nt < 4; nt++) {
                    const int col = wn + nt*8 + 2*tig;
                    atomicAdd(&mp[col],     gt * acc[mt][nt][2*half+0]);
                    atomicAdd(&mp[col + 1], gt * acc[mt][nt][2*half+1]);
                }
            }
        }
    }
}

// ---------------- final: out += moe ----------------
__global__ void final_add(float* __restrict__ out) {
    int i = blockIdx.x * 256 + threadIdx.x;
    float4 a = ((float4*)out)[i];
    float4 bb = ((const float4*)g_moe)[i];
    a.x += bb.x; a.y += bb.y; a.z += bb.z; a.w += bb.w;
    ((float4*)out)[i] = a;
}

// ---------------- launch ----------------
extern "C" void kernel_launch(void* const* d_in, const int* in_sizes, int n_in,
                              void* d_out, int out_size)
{
    const float* x        = (const float*)d_in[0];
    const float* rope_cos = (const float*)d_in[1];
    const float* rope_sin = (const float*)d_in[2];
    const float* attn_nw  = (const float*)d_in[3];
    const float* q_w      = (const float*)d_in[4];
    const float* k_w      = (const float*)d_in[5];
    const float* v_w      = (const float*)d_in[6];
    const float* o_w      = (const float*)d_in[7];
    const float* ffn_nw   = (const float*)d_in[8];
    const float* router_w = (const float*)d_in[9];
    const float* w1       = (const float*)d_in[10];
    const float* w2       = (const float*)d_in[11];
    const float* w3       = (const float*)d_in[12];
    float* out = (float*)d_out;

    float *p_h, *p_qkv, *p_y;
    cudaGetSymbolAddress((void**)&p_h,   g_h);
    cudaGetSymbolAddress((void**)&p_qkv, g_qkv);
    cudaGetSymbolAddress((void**)&p_y,   g_y);

    // 1. zero moe accumulator + expert counters
    zero_kernel<<<(BTn*Cn/4)/256, 256>>>();
    // 2. attention rmsnorm
    rmsnorm_kernel<<<BTn, 256>>>(x, attn_nw, p_h);
    // 3. fused QKV projection (tf32 tensor cores; z selects weight/output)
    gemm_tf32<<<dim3(Cn/128, BTn/128, 3), 256>>>(p_h, q_w, k_w, v_w,
                                                 p_qkv, (size_t)BTn*Cn, nullptr, Cn, Cn);
    // 4. RoPE on q and k
    rope_kernel<<<(2*BTn*Hn*32)/256, 256>>>(rope_cos, rope_sin);
    // 5. causal flash attention
    attn_kernel<<<dim3(Tn/128, Bn*Hn), 128>>>(p_qkv, p_qkv + (size_t)BTn*Cn,
                                              p_qkv + 2*(size_t)BTn*Cn, p_y);
    // 6. O projection + residual -> d_out
    gemm_tf32<<<dim3(Cn/128, BTn/128, 1), 256>>>(p_y, o_w, o_w, o_w,
                                                 out, 0, x, Cn, Cn);
    // 7. ffn rmsnorm (reuse g_h)
    rmsnorm_kernel<<<BTn, 256>>>(out, ffn_nw, p_h);
    // 8. router: top-2 + scatter
    router_kernel<<<BTn, 256>>>(p_h, router_w);
    // 9. expert up-projections (fused w1/w3 + silu gate)
    moe_gemm1_tf32<<<dim3(HDn/64, 4096/128, En), 256>>>(w1, w3);
    // 10. expert down-projection + gated scatter-add
    moe_gemm2_tf32<<<dim3(Cn/128, 4096/128, En), 256>>>(w2);
    // 11. out += moe
    final_add<<<(BTn*Cn/4)/256, 256>>>(out);
}

// round 6
// speedup vs baseline: 2.6127x; 1.4598x over previous
#include <cuda_runtime.h>
#include <math.h>
#include <stdint.h>

#define Bn  2
#define Tn  2048
#define Cn  1024
#define Hn  16
#define Dn  64
#define En  8
#define HDn 1536
#define BTn (Bn*Tn)          // 4096 tokens

// ---------------- scratch (device globals; no allocations allowed) ----------------
__device__ float g_h[BTn*Cn];                       // rmsnorm output (reused for ffn norm)
__device__ float g_qkv[3*BTn*Cn];                   // q | k | v, each [BT][H*D]
__device__ float g_y[BTn*Cn];                       // attention output
__device__ float g_moe[BTn*Cn];                     // MoE accumulation
__device__ float g_g[(size_t)En*4096*HDn];          // gated hidden per expert row block
__device__ int   g_tok[En*4096];
__device__ float g_gate[En*4096];
__device__ int   g_counts[En];

// ---------------- tf32 helpers ----------------
__device__ __forceinline__ uint32_t f2tf32(float x) {
    uint32_t r; asm("cvt.rna.tf32.f32 %0, %1;" : "=r"(r) : "f"(x)); return r;
}
__device__ __forceinline__ uint32_t fu(float x) { return __float_as_uint(x); }
__device__ __forceinline__ void mma8(float* c, uint32_t a0, uint32_t a1, uint32_t a2, uint32_t a3,
                                     uint32_t b0, uint32_t b1) {
    asm volatile("mma.sync.aligned.m16n8k8.row.col.f32.tf32.tf32.f32 "
                 "{%0,%1,%2,%3}, {%4,%5,%6,%7}, {%8,%9}, {%0,%1,%2,%3};\n"
                 : "+f"(c[0]), "+f"(c[1]), "+f"(c[2]), "+f"(c[3])
                 : "r"(a0), "r"(a1), "r"(a2), "r"(a3), "r"(b0), "r"(b1));
}
// fast exp2 on FMA/ALU pipes (rel err ~4e-5 over clamped range)
__device__ __forceinline__ float exp2c(float y) {
    y = fmaxf(y, -50.f);
    float z = y + 12582912.f;                      // 1.5*2^23: round-to-nearest-int
    int ki = __float_as_int(z) - 0x4B400000;
    float f = y - (z - 12582912.f);
    float p = 1.f + f*(0.69314718f + f*(0.24022651f + f*(0.05550411f + f*0.00961813f)));
    return p * __int_as_float((ki + 127) << 23);
}
#define SA 138   // smem row pad (mod 32 == 10): conflict-free STS, near-clean LDS
#define SB 74

#define STS4(buf, kc, row, v) do { \
    buf[(kc)+0][row] = f2tf32((v).x); buf[(kc)+1][row] = f2tf32((v).y); \
    buf[(kc)+2][row] = f2tf32((v).z); buf[(kc)+3][row] = f2tf32((v).w); } while (0)

// ---------------- zero scratch ----------------
__global__ void zero_kernel() {
    int i = blockIdx.x * 256 + threadIdx.x;          // BT*C/4 threads
    ((float4*)g_moe)[i] = make_float4(0.f, 0.f, 0.f, 0.f);
    if (i < En) g_counts[i] = 0;
}

// ---------------- rmsnorm: one block per token ----------------
__global__ __launch_bounds__(256) void rmsnorm_kernel(
    const float* __restrict__ x, const float* __restrict__ w, float* __restrict__ out)
{
    const int t = blockIdx.x;
    const int tid = threadIdx.x;
    const float* xp = x + (size_t)t * Cn;
    float v0 = xp[tid], v1 = xp[tid+256], v2 = xp[tid+512], v3 = xp[tid+768];
    float s = v0*v0 + v1*v1 + v2*v2 + v3*v3;
#pragma unroll
    for (int off = 16; off > 0; off >>= 1) s += __shfl_xor_sync(0xffffffffu, s, off);
    __shared__ float ws[8];
    if ((tid & 31) == 0) ws[tid >> 5] = s;
    __syncthreads();
    float tot = 0.f;
#pragma unroll
    for (int i = 0; i < 8; i++) tot += ws[i];
    const float r = rsqrtf(tot * (1.f/Cn) + 1e-6f);
    float* op = out + (size_t)t * Cn;
    op[tid]     = w[tid]     * v0 * r;
    op[tid+256] = w[tid+256] * v1 * r;
    op[tid+512] = w[tid+512] * v2 * r;
    op[tid+768] = w[tid+768] * v3 * r;
}

// ---------------- tf32 tensor-core GEMM: C[M,N]=A[M,K]@B[N,K]^T (+resid) ----------
__global__ __launch_bounds__(256, 2) void gemm_tf32(
    const float* __restrict__ A,
    const float* __restrict__ B0, const float* __restrict__ B1, const float* __restrict__ B2,
    float* Cbase, size_t cstride,
    const float* __restrict__ resid,
    int Kd, int N)
{
    const int z = blockIdx.z;
    const float* Bmat = (z == 0) ? B0 : (z == 1) ? B1 : B2;
    float* Cm = Cbase + (size_t)z * cstride;
    __shared__ uint32_t As[2][16][SA];
    __shared__ uint32_t Bs[2][16][SA];
    const int tid = threadIdx.x;
    const int bm = blockIdx.y * 128, bn = blockIdx.x * 128;
    const int w = tid >> 5, lane = tid & 31, grp = lane >> 2, tig = lane & 3;
    const int wm = (w & 1) * 64, wn = (w >> 1) * 32;

    const int r0 = tid >> 2, c40 = (tid & 3) << 2;
    const float* Ap0 = A    + (size_t)(bm + r0)      * Kd + c40;
    const float* Ap1 = A    + (size_t)(bm + r0 + 64) * Kd + c40;
    const float* Bp0 = Bmat + (size_t)(bn + r0)      * Kd + c40;
    const float* Bp1 = Bmat + (size_t)(bn + r0 + 64) * Kd + c40;

    float acc[4][4][4];
#pragma unroll
    for (int mt = 0; mt < 4; mt++)
#pragma unroll
        for (int nt = 0; nt < 4; nt++)
#pragma unroll
            for (int i = 0; i < 4; i++) acc[mt][nt][i] = 0.f;

    float4 ra0 = *(const float4*)Ap0, ra1 = *(const float4*)Ap1;
    float4 rb0 = *(const float4*)Bp0, rb1 = *(const float4*)Bp1;
    STS4(As[0], c40, r0,      ra0); STS4(As[0], c40, r0 + 64, ra1);
    STS4(Bs[0], c40, r0,      rb0); STS4(Bs[0], c40, r0 + 64, rb1);
    __syncthreads();

    const int NT = Kd >> 4;
    for (int kt = 0; kt < NT; kt++) {
        const int cur = kt & 1;
        if (kt + 1 < NT) {
            const int ko = (kt + 1) << 4;
            ra0 = *(const float4*)(Ap0 + ko); ra1 = *(const float4*)(Ap1 + ko);
            rb0 = *(const float4*)(Bp0 + ko); rb1 = *(const float4*)(Bp1 + ko);
        }
#pragma unroll
        for (int kb = 0; kb < 16; kb += 8) {
            uint32_t bf[4][2];
#pragma unroll
            for (int nt = 0; nt < 4; nt++) {
                const int n0 = wn + nt*8 + grp;
                bf[nt][0] = Bs[cur][kb + tig][n0];
                bf[nt][1] = Bs[cur][kb + tig + 4][n0];
            }
#pragma unroll
            for (int mt = 0; mt < 4; mt++) {
                const int m0 = wm + mt*16 + grp;
                uint32_t a0 = As[cur][kb + tig][m0];
                uint32_t a1 = As[cur][kb + tig][m0 + 8];
                uint32_t a2 = As[cur][kb + tig + 4][m0];
                uint32_t a3 = As[cur][kb + tig + 4][m0 + 8];
#pragma unroll
                for (int nt = 0; nt < 4; nt++)
                    mma8(acc[mt][nt], a0, a1, a2, a3, bf[nt][0], bf[nt][1]);
            }
        }
        if (kt + 1 < NT) {
            const int nx = cur ^ 1;
            STS4(As[nx], c40, r0,      ra0); STS4(As[nx], c40, r0 + 64, ra1);
            STS4(Bs[nx], c40, r0,      rb0); STS4(Bs[nx], c40, r0 + 64, rb1);
        }
        __syncthreads();
    }
#pragma unroll
    for (int mt = 0; mt < 4; mt++) {
        const int rg = bm + wm + mt*16 + grp;
#pragma unroll
        for (int nt = 0; nt < 4; nt++) {
            const int col = bn + wn + nt*8 + 2*tig;
            float2 v0 = make_float2(acc[mt][nt][0], acc[mt][nt][1]);
            float2 v1 = make_float2(acc[mt][nt][2], acc[mt][nt][3]);
            if (resid) {
                float2 s0 = *(const float2*)&resid[(size_t)rg*N + col];
                float2 s1 = *(const float2*)&resid[(size_t)(rg+8)*N + col];
                v0.x += s0.x; v0.y += s0.y; v1.x += s1.x; v1.y += s1.y;
            }
            *(float2*)&Cm[(size_t)rg*N + col]     = v0;
            *(float2*)&Cm[(size_t)(rg+8)*N + col] = v1;
        }
    }
}

// ---------------- RoPE (in-place on q and k halves of g_qkv) ----------------
__global__ __launch_bounds__(256) void rope_kernel(
    const float* __restrict__ cosb, const float* __restrict__ sinb)
{
    const int NQ = BTn * Hn * 32;                    // 2^21 pairs per tensor
    int idx = blockIdx.x * 256 + threadIdx.x;        // 0 .. 2*NQ-1
    float* buf = g_qkv + (idx >= NQ ? (size_t)BTn * Cn : 0);
    int i  = idx & (NQ - 1);
    int d  = i & 31;
    int bh = i >> 5;                                  // (b*T + t)*H + h
    int t  = (bh >> 4) & (Tn - 1);
    size_t base = (size_t)bh * 64;
    float x1 = buf[base + d];
    float x2 = buf[base + d + 32];
    float c1 = cosb[t*64 + d],      s1 = sinb[t*64 + d];
    float c2 = cosb[t*64 + d + 32], s2 = sinb[t*64 + d + 32];
    buf[base + d]      = x1 * c1 - x2 * s1;
    buf[base + d + 32] = x2 * c2 + x1 * s2;
}

// ---------------- tensor-core causal flash attention (tf32 warp MMA) ----------
// Block: 64 q-rows, 4 warps x 16 rows. K-tiles of 64. Dynamic smem:
//   Ks[64][PK] (d-major = B operand for S), Vs[64][PV], Ps[64][PP] (P roundtrip + Q staging)
#define PK 67
#define PV 68
#define PP 68
#define SMEM_ATTN ((64*PK + 64*PV + 64*PP) * 4)

__global__ __launch_bounds__(128, 3) void attn_mma(
    const float* __restrict__ q, const float* __restrict__ k,
    const float* __restrict__ v, float* __restrict__ y)
{
    extern __shared__ float sm[];
    float* Ks = sm;
    float* Vs = Ks + 64*PK;
    float* Ps = Vs + 64*PV;

    const int tid = threadIdx.x;
    const int w = tid >> 5, lane = tid & 31, grp = lane >> 2, tig = lane & 3;
    const int wm = w * 16;
    const int bh = blockIdx.y, b = bh >> 4, h = bh & 15;
    const int bq = (gridDim.x - 1 - blockIdx.x) * 64;     // longest blocks first

    const int rowstride = Hn * Dn;                         // 1024
    const size_t base = ((size_t)b * Tn * Hn + h) * Dn;

    // ---- stage Q (scaled by 0.125*log2e) into Ps area, extract A-fragments ----
    const float qscale = 0.125f * 1.44269504088896341f;
#pragma unroll
    for (int i = 0; i < 8; i++) {
        int linear = (i*128 + tid) * 4;
        int row = linear >> 6, col = linear & 63;
        float4 t4 = *(const float4*)&q[base + (size_t)(bq + row) * rowstride + col];
        float* dst = &Ps[row*PP + col];
        dst[0] = t4.x*qscale; dst[1] = t4.y*qscale; dst[2] = t4.z*qscale; dst[3] = t4.w*qscale;
    }
    __syncthreads();
    uint32_t qa[8][4];
#pragma unroll
    for (int kb = 0; kb < 8; kb++) {
        qa[kb][0] = f2tf32(Ps[(wm+grp)  *PP + kb*8 + tig]);
        qa[kb][1] = f2tf32(Ps[(wm+grp+8)*PP + kb*8 + tig]);
        qa[kb][2] = f2tf32(Ps[(wm+grp)  *PP + kb*8 + tig + 4]);
        qa[kb][3] = f2tf32(Ps[(wm+grp+8)*PP + kb*8 + tig + 4]);
    }
    __syncthreads();

    float o[8][4];
#pragma unroll
    for (int dt = 0; dt < 8; dt++)
#pragma unroll
        for (int i = 0; i < 4; i++) o[dt][i] = 0.f;
    float m0 = -1e30f, m1 = -1e30f, l0 = 0.f, l1 = 0.f;

    const int ktE = bq >> 6;
    for (int kt = 0; kt <= ktE; kt++) {
        // ---- load K-tile (transposed into d-major) and V-tile ----
#pragma unroll
        for (int i = 0; i < 8; i++) {
            int linear = (i*128 + tid) * 4;
            int row = linear >> 6, col = linear & 63;      // row = key index, col = d
            size_t gof = base + (size_t)(kt*64 + row) * rowstride + col;
            float4 kv = *(const float4*)&k[gof];
            Ks[(col+0)*PK + row] = kv.x;
            Ks[(col+1)*PK + row] = kv.y;
            Ks[(col+2)*PK + row] = kv.z;
            Ks[(col+3)*PK + row] = kv.w;
            *(float4*)&Vs[row*PV + col] = *(const float4*)&v[gof];
        }
        __syncthreads();

        // ---- S = Q @ K^T (16x64 per warp) ----
        float s[8][4];
#pragma unroll
        for (int nt = 0; nt < 8; nt++) {
            s[nt][0] = 0.f; s[nt][1] = 0.f; s[nt][2] = 0.f; s[nt][3] = 0.f;
#pragma unroll
            for (int kb = 0; kb < 8; kb++) {
                uint32_t b0 = fu(Ks[(kb*8 + tig)    *PK + nt*8 + grp]);
                uint32_t b1 = fu(Ks[(kb*8 + tig + 4)*PK + nt*8 + grp]);
                mma8(s[nt], qa[kb][0], qa[kb][1], qa[kb][2], qa[kb][3], b0, b1);
            }
        }

        // ---- causal mask (diagonal tile only; local col vs local row) ----
        if (kt == ktE) {
#pragma unroll
            for (int nt = 0; nt < 8; nt++) {
                int coll = nt*8 + 2*tig;
                if (coll     > wm + grp)     s[nt][0] = -1e30f;
                if (coll + 1 > wm + grp)     s[nt][1] = -1e30f;
                if (coll     > wm + grp + 8) s[nt][2] = -1e30f;
                if (coll + 1 > wm + grp + 8) s[nt][3] = -1e30f;
            }
        }

        // ---- online softmax (base-2; q pre-scaled) ----
        float t0 = -1e30f, t1 = -1e30f;
#pragma unroll
        for (int nt = 0; nt < 8; nt++) {
            t0 = fmaxf(t0, fmaxf(s[nt][0], s[nt][1]));
            t1 = fmaxf(t1, fmaxf(s[nt][2], s[nt][3]));
        }
        t0 = fmaxf(t0, __shfl_xor_sync(0xffffffffu, t0, 1));
        t0 = fmaxf(t0, __shfl_xor_sync(0xffffffffu, t0, 2));
        t1 = fmaxf(t1, __shfl_xor_sync(0xffffffffu, t1, 1));
        t1 = fmaxf(t1, __shfl_xor_sync(0xffffffffu, t1, 2));
        float m0n = fmaxf(m0, t0), m1n = fmaxf(m1, t1);
        float scl0 = exp2c(m0 - m0n), scl1 = exp2c(m1 - m1n);
        m0 = m0n; m1 = m1n;
        float lp0 = 0.f, lp1 = 0.f;
#pragma unroll
        for (int nt = 0; nt < 8; nt++) {
            s[nt][0] = exp2c(s[nt][0] - m0); s[nt][1] = exp2c(s[nt][1] - m0);
            s[nt][2] = exp2c(s[nt][2] - m1); s[nt][3] = exp2c(s[nt][3] - m1);
            lp0 += s[nt][0] + s[nt][1];
            lp1 += s[nt][2] + s[nt][3];
        }
        l0 = l0 * scl0 + lp0;
        l1 = l1 * scl1 + lp1;
#pragma unroll
        for (int dt = 0; dt < 8; dt++) {
            o[dt][0] *= scl0; o[dt][1] *= scl0; o[dt][2] *= scl1; o[dt][3] *= scl1;
        }

        // ---- P -> smem (C-frag layout) then reload as A-frags ----
#pragma unroll
        for (int nt = 0; nt < 8; nt++) {
            *(float2*)&Ps[(wm+grp)  *PP + nt*8 + 2*tig] = make_float2(s[nt][0], s[nt][1]);
            *(float2*)&Ps[(wm+grp+8)*PP + nt*8 + 2*tig] = make_float2(s[nt][2], s[nt][3]);
        }
        __syncwarp();

        // ---- O += P @ V ----
#pragma unroll
        for (int kb = 0; kb < 8; kb++) {
            uint32_t a0 = fu(Ps[(wm+grp)  *PP + kb*8 + tig]);
            uint32_t a1 = fu(Ps[(wm+grp+8)*PP + kb*8 + tig]);
            uint32_t a2 = fu(Ps[(wm+grp)  *PP + kb*8 + tig + 4]);
            uint32_t a3 = fu(Ps[(wm+grp+8)*PP + kb*8 + tig + 4]);
#pragma unroll
            for (int dt = 0; dt < 8; dt++) {
                uint32_t b0 = fu(Vs[(kb*8 + tig)    *PV + dt*8 + grp]);
                uint32_t b1 = fu(Vs[(kb*8 + tig + 4)*PV + dt*8 + grp]);
                mma8(o[dt], a0, a1, a2, a3, b0, b1);
            }
        }
        __syncthreads();
    }

    // ---- epilogue: reduce l across quad, normalize, store ----
    l0 += __shfl_xor_sync(0xffffffffu, l0, 1);
    l0 += __shfl_xor_sync(0xffffffffu, l0, 2);
    l1 += __shfl_xor_sync(0xffffffffu, l1, 1);
    l1 += __shfl_xor_sync(0xffffffffu, l1, 2);
    const float inv0 = 1.f / l0, inv1 = 1.f / l1;
    const int r0g = bq + wm + grp, r1g = r0g + 8;
#pragma unroll
    for (int dt = 0; dt < 8; dt++) {
        const int col = dt*8 + 2*tig;
        *(float2*)&y[base + (size_t)r0g*rowstride + col] =
            make_float2(o[dt][0]*inv0, o[dt][1]*inv0);
        *(float2*)&y[base + (size_t)r1g*rowstride + col] =
            make_float2(o[dt][2]*inv1, o[dt][3]*inv1);
    }
}

// ---------------- router ----------------
__global__ __launch_bounds__(256) void router_kernel(
    const float* __restrict__ hn, const float* __restrict__ rw)
{
    const int t = blockIdx.x;
    const int tid = threadIdx.x;
    const int lane = tid & 31, w = tid >> 5;
    __shared__ float logits[8];
    const float* xp = hn + (size_t)t * Cn;
    const float* wp = rw + (size_t)w * Cn;
    float s = 0.f;
    for (int c = lane; c < Cn; c += 32) s = fmaf(xp[c], wp[c], s);
#pragma unroll
    for (int off = 16; off > 0; off >>= 1) s += __shfl_xor_sync(0xffffffffu, s, off);
    if (lane == 0) logits[w] = s;
    __syncthreads();
    if (tid == 0) {
        float l0 = logits[0]; int e0 = 0;
#pragma unroll
        for (int e = 1; e < 8; e++) if (logits[e] > l0) { l0 = logits[e]; e0 = e; }
        float l1 = -INFINITY; int e1 = 0;
#pragma unroll
        for (int e = 0; e < 8; e++) if (e != e0 && logits[e] > l1) { l1 = logits[e]; e1 = e; }
        float g0 = 1.f / (1.f + __expf(l1 - l0));
        float g1 = 1.f - g0;
        int p0 = atomicAdd(&g_counts[e0], 1);
        g_tok[e0*4096 + p0] = t; g_gate[e0*4096 + p0] = g0;
        int p1 = atomicAdd(&g_counts[e1], 1);
        g_tok[e1*4096 + p1] = t; g_gate[e1*4096 + p1] = g1;
    }
}

// ---------------- MoE GEMM1 (tf32): G = silu(X@w1^T)*(X@w3^T), gathered rows ----
__global__ __launch_bounds__(256, 2) void moe_gemm1_tf32(
    const float* __restrict__ w1, const float* __restrict__ w3)
{
    const int e = blockIdx.z;
    const int cnt = g_counts[e];
    const int bm = blockIdx.y * 128;
    if (bm >= cnt) return;
    const int bn = blockIdx.x * 64;
    __shared__ uint32_t As[2][16][SA];
    __shared__ uint32_t B1s[2][16][SB];
    __shared__ uint32_t B3s[2][16][SB];
    __shared__ int rowtok[128];
    const int tid = threadIdx.x;
    if (tid < 128) {
        int r = bm + tid;
        rowtok[tid] = g_tok[e*4096 + ((r < cnt) ? r : 0)];
    }
    __syncthreads();
    const float* W1 = w1 + (size_t)e * HDn * Cn;
    const float* W3 = w3 + (size_t)e * HDn * Cn;
    const int w = tid >> 5, lane = tid & 31, grp = lane >> 2, tig = lane & 3;
    const int wm = (w & 3) * 32, wn = (w >> 2) * 32;

    const int r0 = tid >> 2, c40 = (tid & 3) << 2;
    const float* Ap0 = g_h + (size_t)rowtok[r0]      * Cn + c40;
    const float* Ap1 = g_h + (size_t)rowtok[r0 + 64] * Cn + c40;
    const float* B1p = W1  + (size_t)(bn + r0) * Cn + c40;
    const float* B3p = W3  + (size_t)(bn + r0) * Cn + c40;

    float acc1[2][4][4], acc3[2][4][4];
#pragma unroll
    for (int mt = 0; mt < 2; mt++)
#pragma unroll
        for (int nt = 0; nt < 4; nt++)
#pragma unroll
            for (int i = 0; i < 4; i++) { acc1[mt][nt][i] = 0.f; acc3[mt][nt][i] = 0.f; }

    float4 ra0 = *(const float4*)Ap0, ra1 = *(const float4*)Ap1;
    float4 rb1 = *(const float4*)B1p, rb3 = *(const float4*)B3p;
    STS4(As[0], c40, r0, ra0); STS4(As[0], c40, r0 + 64, ra1);
    STS4(B1s[0], c40, r0, rb1); STS4(B3s[0], c40, r0, rb3);
    __syncthreads();

    const int NT = Cn >> 4;
    for (int kt = 0; kt < NT; kt++) {
        const int cur = kt & 1;
        if (kt + 1 < NT) {
            const int ko = (kt + 1) << 4;
            ra0 = *(const float4*)(Ap0 + ko); ra1 = *(const float4*)(Ap1 + ko);
            rb1 = *(const float4*)(B1p + ko); rb3 = *(const float4*)(B3p + ko);
        }
#pragma unroll
        for (int kb = 0; kb < 16; kb += 8) {
            uint32_t bf1[4][2], bf3[4][2];
#pragma unroll
            for (int nt = 0; nt < 4; nt++) {
                const int n0 = wn + nt*8 + grp;
                bf1[nt][0] = B1s[cur][kb + tig][n0];
                bf1[nt][1] = B1s[cur][kb + tig + 4][n0];
                bf3[nt][0] = B3s[cur][kb + tig][n0];
                bf3[nt][1] = B3s[cur][kb + tig + 4][n0];
            }
#pragma unroll
            for (int mt = 0; mt < 2; mt++) {
                const int m0 = wm + mt*16 + grp;
                uint32_t a0 = As[cur][kb + tig][m0];
                uint32_t a1 = As[cur][kb + tig][m0 + 8];
                uint32_t a2 = As[cur][kb + tig + 4][m0];
                uint32_t a3 = As[cur][kb + tig + 4][m0 + 8];
#pragma unroll
                for (int nt = 0; nt < 4; nt++) {
                    mma8(acc1[mt][nt], a0, a1, a2, a3, bf1[nt][0], bf1[nt][1]);
                    mma8(acc3[mt][nt], a0, a1, a2, a3, bf3[nt][0], bf3[nt][1]);
                }
            }
        }
        if (kt + 1 < NT) {
            const int nx = cur ^ 1;
            STS4(As[nx], c40, r0, ra0); STS4(As[nx], c40, r0 + 64, ra1);
            STS4(B1s[nx], c40, r0, rb1); STS4(B3s[nx], c40, r0, rb3);
        }
        __syncthreads();
    }
#pragma unroll
    for (int mt = 0; mt < 2; mt++) {
#pragma unroll
        for (int half = 0; half < 2; half++) {
            const int rl = wm + mt*16 + grp + half*8;
            if (bm + rl < cnt) {
                float* gp = &g_g[((size_t)e*4096 + bm + rl)*HDn + bn];
#pragma unroll
                for (int nt = 0; nt < 4; nt++) {
                    const int col = wn + nt*8 + 2*tig;
                    float u0 = acc1[mt][nt][2*half+0], v0 = acc3[mt][nt][2*half+0];
                    float u1 = acc1[mt][nt][2*half+1], v1 = acc3[mt][nt][2*half+1];
                    float g0 = u0 / (1.f + __expf(-u0)) * v0;
                    float g1 = u1 / (1.f + __expf(-u1)) * v1;
                    *(float2*)&gp[col] = make_float2(g0, g1);
                }
            }
        }
    }
}

// ---------------- MoE GEMM2 (tf32): Y = G @ w2^T, gated scatter-add -----------
__global__ __launch_bounds__(256, 2) void moe_gemm2_tf32(const float* __restrict__ w2)
{
    const int e = blockIdx.z;
    const int cnt = g_counts[e];
    const int bm = blockIdx.y * 128;
    if (bm >= cnt) return;
    const int bn = blockIdx.x * 128;
    __shared__ uint32_t As[2][16][SA];
    __shared__ uint32_t Bs[2][16][SA];
    const float* Am = g_g + (size_t)e * 4096 * HDn;
    const float* Bmat = w2 + (size_t)e * Cn * HDn;
    const int tid = threadIdx.x;
    const int w = tid >> 5, lane = tid & 31, grp = lane >> 2, tig = lane & 3;
    const int wm = (w & 1) * 64, wn = (w >> 1) * 32;

    const int r0 = tid >> 2, c40 = (tid & 3) << 2;
    const float* Ap0 = Am   + (size_t)(bm + r0)      * HDn + c40;
    const float* Ap1 = Am   + (size_t)(bm + r0 + 64) * HDn + c40;
    const float* Bp0 = Bmat + (size_t)(bn + r0)      * HDn + c40;
    const float* Bp1 = Bmat + (size_t)(bn + r0 + 64) * HDn + c40;

    float acc[4][4][4];
#pragma unroll
    for (int mt = 0; mt < 4; mt++)
#pragma unroll
        for (int nt = 0; nt < 4; nt++)
#pragma unroll
            for (int i = 0; i < 4; i++) acc[mt][nt][i] = 0.f;

    float4 ra0 = *(const float4*)Ap0, ra1 = *(const float4*)Ap1;
    float4 rb0 = *(const float4*)Bp0, rb1 = *(const float4*)Bp1;
    STS4(As[0], c40, r0, ra0); STS4(As[0], c40, r0 + 64, ra1);
    STS4(Bs[0], c40, r0, rb0); STS4(Bs[0], c40, r0 + 64, rb1);
    __syncthreads();

    const int NT = HDn >> 4;
    for (int kt = 0; kt < NT; kt++) {
        const int cur = kt & 1;
        if (kt + 1 < NT) {
            const int ko = (kt + 1) << 4;
            ra0 = *(const float4*)(Ap0 + ko); ra1 = *(const float4*)(Ap1 + ko);
            rb0 = *(const float4*)(Bp0 + ko); rb1 = *(const float4*)(Bp1 + ko);
        }
#pragma unroll
        for (int kb = 0; kb < 16; kb += 8) {
            uint32_t bf[4][2];
#pragma unroll
            for (int nt = 0; nt < 4; nt++) {
                const int n0 = wn + nt*8 + grp;
                bf[nt][0] = Bs[cur][kb + tig][n0];
                bf[nt][1] = Bs[cur][kb + tig + 4][n0];
            }
#pragma unroll
            for (int mt = 0; mt < 4; mt++) {
                const int m0 = wm + mt*16 + grp;
                uint32_t a0 = As[cur][kb + tig][m0];
                uint32_t a1 = As[cur][kb + tig][m0 + 8];
                uint32_t a2 = As[cur][kb + tig + 4][m0];
                uint32_t a3 = As[cur][kb + tig + 4][m0 + 8];
#pragma unroll
                for (int nt = 0; nt < 4; nt++)
                    mma8(acc[mt][nt], a0, a1, a2, a3, bf[nt][0], bf[nt][1]);
            }
        }
        if (kt + 1 < NT) {
            const int nx = cur ^ 1;
            STS4(As[nx], c40, r0, ra0); STS4(As[nx], c40, r0 + 64, ra1);
            STS4(Bs[nx], c40, r0, rb0); STS4(Bs[nx], c40, r0 + 64, rb1);
        }
        __syncthreads();
    }
#pragma unroll
    for (int mt = 0; mt < 4; mt++) {
#pragma unroll
        for (int half = 0; half < 2; half++) {
            const int rl = wm + mt*16 + grp + half*8;
            if (bm + rl < cnt) {
                const int tok = g_tok[e*4096 + bm + rl];
                const float gt = g_gate[e*4096 + bm + rl];
                float* mp = &g_moe[(size_t)tok*Cn + bn];
#pragma unroll
                for (int nt = 0; nt < 4; nt++) {
                    const int col = wn + nt*8 + 2*tig;
                    atomicAdd(&mp[col],     gt * acc[mt][nt][2*half+0]);
                    atomicAdd(&mp[col + 1], gt * acc[mt][nt][2*half+1]);
                }
            }
        }
    }
}

// ---------------- final: out += moe ----------------
__global__ void final_add(float* __restrict__ out) {
    int i = blockIdx.x * 256 + threadIdx.x;
    float4 a = ((float4*)out)[i];
    float4 bb = ((const float4*)g_moe)[i];
    a.x += bb.x; a.y += bb.y; a.z += bb.z; a.w += bb.w;
    ((float4*)out)[i] = a;
}

// ---------------- launch ----------------
extern "C" void kernel_launch(void* const* d_in, const int* in_sizes, int n_in,
                              void* d_out, int out_size)
{
    const float* x        = (const float*)d_in[0];
    const float* rope_cos = (const float*)d_in[1];
    const float* rope_sin = (const float*)d_in[2];
    const float* attn_nw  = (const float*)d_in[3];
    const float* q_w      = (const float*)d_in[4];
    const float* k_w      = (const float*)d_in[5];
    const float* v_w      = (const float*)d_in[6];
    const float* o_w      = (const float*)d_in[7];
    const float* ffn_nw   = (const float*)d_in[8];
    const float* router_w = (const float*)d_in[9];
    const float* w1       = (const float*)d_in[10];
    const float* w2       = (const float*)d_in[11];
    const float* w3       = (const float*)d_in[12];
    float* out = (float*)d_out;

    float *p_h, *p_qkv, *p_y;
    cudaGetSymbolAddress((void**)&p_h,   g_h);
    cudaGetSymbolAddress((void**)&p_qkv, g_qkv);
    cudaGetSymbolAddress((void**)&p_y,   g_y);

    static int attn_attr_set = 0;
    if (!attn_attr_set) {
        cudaFuncSetAttribute(attn_mma, cudaFuncAttributeMaxDynamicSharedMemorySize, SMEM_ATTN);
        attn_attr_set = 1;
    }

    // 1. zero moe accumulator + expert counters
    zero_kernel<<<(BTn*Cn/4)/256, 256>>>();
    // 2. attention rmsnorm
    rmsnorm_kernel<<<BTn, 256>>>(x, attn_nw, p_h);
    // 3. fused QKV projection (tf32 tensor cores; z selects weight/output)
    gemm_tf32<<<dim3(Cn/128, BTn/128, 3), 256>>>(p_h, q_w, k_w, v_w,
                                                 p_qkv, (size_t)BTn*Cn, nullptr, Cn, Cn);
    // 4. RoPE on q and k
    rope_kernel<<<(2*BTn*Hn*32)/256, 256>>>(rope_cos, rope_sin);
    // 5. causal flash attention (tf32 warp MMA)
    attn_mma<<<dim3(Tn/64, Bn*Hn), 128, SMEM_ATTN>>>(p_qkv, p_qkv + (size_t)BTn*Cn,
                                                     p_qkv + 2*(size_t)BTn*Cn, p_y);
    // 6. O projection + residual -> d_out
    gemm_tf32<<<dim3(Cn/128, BTn/128, 1), 256>>>(p_y, o_w, o_w, o_w,
                                                 out, 0, x, Cn, Cn);
    // 7. ffn rmsnorm (reuse g_h)
    rmsnorm_kernel<<<BTn, 256>>>(out, ffn_nw, p_h);
    // 8. router: top-2 + scatter
    router_kernel<<<BTn, 256>>>(p_h, router_w);
    // 9. expert up-projections (fused w1/w3 + silu gate)
    moe_gemm1_tf32<<<dim3(HDn/64, 4096/128, En), 256>>>(w1, w3);
    // 10. expert down-projection + gated scatter-add
    moe_gemm2_tf32<<<dim3(Cn/128, 4096/128, En), 256>>>(w2);
    // 11. out += moe
    final_add<<<(BTn*Cn/4)/256, 256>>>(out);
}

// round 9
// speedup vs baseline: 3.7011x; 1.4166x over previous
#include <cuda_runtime.h>
#include <cuda_bf16.h>
#include <math.h>
#include <stdint.h>

#define Bn  2
#define Tn  2048
#define Cn  1024
#define Hn  16
#define Dn  64
#define En  8
#define HDn 1536
#define BTn (Bn*Tn)          // 4096 tokens

// ---------------- scratch (device globals; no allocations allowed) ----------------
__device__ float g_h[BTn*Cn];                       // rmsnorm output (reused for ffn norm)
__device__ float g_qkv[3*BTn*Cn];                   // q | k | v, each [BT][H*D]
__device__ float g_y[BTn*Cn];                       // attention output
__device__ float g_moe[BTn*Cn];                     // MoE accumulation
__device__ float g_g[(size_t)En*4096*HDn];          // gated hidden per expert row block
__device__ int   g_tok[En*4096];
__device__ float g_gate[En*4096];
__device__ int   g_counts[En];

// ---------------- helpers ----------------
__device__ __forceinline__ uint32_t f2tf32(float x) {
    uint32_t r; asm("cvt.rna.tf32.f32 %0, %1;" : "=r"(r) : "f"(x)); return r;
}
__device__ __forceinline__ uint32_t fu(float x) { return __float_as_uint(x); }
__device__ __forceinline__ uint32_t pk2(float lo, float hi) {
    __nv_bfloat162 p = __floats2bfloat162_rn(lo, hi);
    return *(uint32_t*)&p;
}
__device__ __forceinline__ void mma8(float* c, uint32_t a0, uint32_t a1, uint32_t a2, uint32_t a3,
                                     uint32_t b0, uint32_t b1) {
    asm volatile("mma.sync.aligned.m16n8k8.row.col.f32.tf32.tf32.f32 "
                 "{%0,%1,%2,%3}, {%4,%5,%6,%7}, {%8,%9}, {%0,%1,%2,%3};\n"
                 : "+f"(c[0]), "+f"(c[1]), "+f"(c[2]), "+f"(c[3])
                 : "r"(a0), "r"(a1), "r"(a2), "r"(a3), "r"(b0), "r"(b1));
}
__device__ __forceinline__ void mma16(float* c, uint32_t a0, uint32_t a1, uint32_t a2, uint32_t a3,
                                      uint32_t b0, uint32_t b1) {
    asm volatile("mma.sync.aligned.m16n8k16.row.col.f32.bf16.bf16.f32 "
                 "{%0,%1,%2,%3}, {%4,%5,%6,%7}, {%8,%9}, {%0,%1,%2,%3};\n"
                 : "+f"(c[0]), "+f"(c[1]), "+f"(c[2]), "+f"(c[3])
                 : "r"(a0), "r"(a1), "r"(a2), "r"(a3), "r"(b0), "r"(b1));
}
// fast exp2 on FMA/ALU pipes (rel err ~4e-5 over clamped range)
__device__ __forceinline__ float exp2c(float y) {
    y = fmaxf(y, -50.f);
    float z = y + 12582912.f;                      // 1.5*2^23: round-to-nearest-int
    int ki = __float_as_int(z) - 0x4B400000;
    float f = y - (z - 12582912.f);
    float p = 1.f + f*(0.69314718f + f*(0.24022651f + f*(0.05550411f + f*0.00961813f)));
    return p * __int_as_float((ki + 127) << 23);
}
#define PA 132   // bf16x2 smem row pad for 128-wide tiles: STS hits all 32 banks once
#define PB 68    // same property for 64-wide tiles

// pack float4 (4 consecutive k) into two bf16x2 at k2 rows
#define STSB(buf, k2, row, v) do { \
    buf[(k2)+0][row] = pk2((v).x, (v).y); \
    buf[(k2)+1][row] = pk2((v).z, (v).w); } while (0)

// ---------------- zero scratch ----------------
__global__ void zero_kernel() {
    int i = blockIdx.x * 256 + threadIdx.x;          // BT*C/4 threads
    ((float4*)g_moe)[i] = make_float4(0.f, 0.f, 0.f, 0.f);
    if (i < En) g_counts[i] = 0;
}

// ---------------- rmsnorm: one block per token ----------------
__global__ __launch_bounds__(256) void rmsnorm_kernel(
    const float* __restrict__ x, const float* __restrict__ w, float* __restrict__ out)
{
    const int t = blockIdx.x;
    const int tid = threadIdx.x;
    const float* xp = x + (size_t)t * Cn;
    float v0 = xp[tid], v1 = xp[tid+256], v2 = xp[tid+512], v3 = xp[tid+768];
    float s = v0*v0 + v1*v1 + v2*v2 + v3*v3;
#pragma unroll
    for (int off = 16; off > 0; off >>= 1) s += __shfl_xor_sync(0xffffffffu, s, off);
    __shared__ float ws[8];
    if ((tid & 31) == 0) ws[tid >> 5] = s;
    __syncthreads();
    float tot = 0.f;
#pragma unroll
    for (int i = 0; i < 8; i++) tot += ws[i];
    const float r = rsqrtf(tot * (1.f/Cn) + 1e-6f);
    float* op = out + (size_t)t * Cn;
    op[tid]     = w[tid]     * v0 * r;
    op[tid+256] = w[tid+256] * v1 * r;
    op[tid+512] = w[tid+512] * v2 * r;
    op[tid+768] = w[tid+768] * v3 * r;
}

// ---------------- bf16 tensor-core GEMM: C[M,N]=A[M,K]@B[N,K]^T (+resid) ----------
// 128x128 block, 8 warps (2m x 4n), warp tile 64x32, BK=16, double buffered.
__global__ __launch_bounds__(256, 2) void gemm_bf16(
    const float* __restrict__ A,
    const float* __restrict__ B0, const float* __restrict__ B1, const float* __restrict__ B2,
    float* Cbase, size_t cstride,
    const float* __restrict__ resid,
    int Kd, int N)
{
    const int z = blockIdx.z;
    const float* Bmat = (z == 0) ? B0 : (z == 1) ? B1 : B2;
    float* Cm = Cbase + (size_t)z * cstride;
    __shared__ uint32_t As[2][8][PA];
    __shared__ uint32_t Bs[2][8][PA];
    const int tid = threadIdx.x;
    const int bm = blockIdx.y * 128, bn = blockIdx.x * 128;
    const int w = tid >> 5, lane = tid & 31, grp = lane >> 2, tig = lane & 3;
    const int wm = (w & 1) * 64, wn = (w >> 1) * 32;

    const int r0 = tid >> 2, c40 = (tid & 3) << 2, k20 = (tid & 3) << 1;
    const float* Ap0 = A    + (size_t)(bm + r0)      * Kd + c40;
    const float* Ap1 = A    + (size_t)(bm + r0 + 64) * Kd + c40;
    const float* Bp0 = Bmat + (size_t)(bn + r0)      * Kd + c40;
    const float* Bp1 = Bmat + (size_t)(bn + r0 + 64) * Kd + c40;

    float acc[4][4][4];
#pragma unroll
    for (int mt = 0; mt < 4; mt++)
#pragma unroll
        for (int nt = 0; nt < 4; nt++)
#pragma unroll
            for (int i = 0; i < 4; i++) acc[mt][nt][i] = 0.f;

    float4 ra0 = *(const float4*)Ap0, ra1 = *(const float4*)Ap1;
    float4 rb0 = *(const float4*)Bp0, rb1 = *(const float4*)Bp1;
    STSB(As[0], k20, r0,      ra0); STSB(As[0], k20, r0 + 64, ra1);
    STSB(Bs[0], k20, r0,      rb0); STSB(Bs[0], k20, r0 + 64, rb1);
    __syncthreads();

    const int NT = Kd >> 4;
    for (int kt = 0; kt < NT; kt++) {
        const int cur = kt & 1;
        if (kt + 1 < NT) {
            const int ko = (kt + 1) << 4;
            ra0 = *(const float4*)(Ap0 + ko); ra1 = *(const float4*)(Ap1 + ko);
            rb0 = *(const float4*)(Bp0 + ko); rb1 = *(const float4*)(Bp1 + ko);
        }
        {
            uint32_t bf[4][2];
#pragma unroll
            for (int nt = 0; nt < 4; nt++) {
                const int n0 = wn + nt*8 + grp;
                bf[nt][0] = Bs[cur][tig][n0];
                bf[nt][1] = Bs[cur][tig + 4][n0];
            }
#pragma unroll
            for (int mt = 0; mt < 4; mt++) {
                const int m0 = wm + mt*16 + grp;
                uint32_t a0 = As[cur][tig][m0];
                uint32_t a1 = As[cur][tig][m0 + 8];
                uint32_t a2 = As[cur][tig + 4][m0];
                uint32_t a3 = As[cur][tig + 4][m0 + 8];
#pragma unroll
                for (int nt = 0; nt < 4; nt++)
                    mma16(acc[mt][nt], a0, a1, a2, a3, bf[nt][0], bf[nt][1]);
            }
        }
        if (kt + 1 < NT) {
            const int nx = cur ^ 1;
            STSB(As[nx], k20, r0,      ra0); STSB(As[nx], k20, r0 + 64, ra1);
            STSB(Bs[nx], k20, r0,      rb0); STSB(Bs[nx], k20, r0 + 64, rb1);
        }
        __syncthreads();
    }
#pragma unroll
    for (int mt = 0; mt < 4; mt++) {
        const int rg = bm + wm + mt*16 + grp;
#pragma unroll
        for (int nt = 0; nt < 4; nt++) {
            const int col = bn + wn + nt*8 + 2*tig;
            float2 v0 = make_float2(acc[mt][nt][0], acc[mt][nt][1]);
            float2 v1 = make_float2(acc[mt][nt][2], acc[mt][nt][3]);
            if (resid) {
                float2 s0 = *(const float2*)&resid[(size_t)rg*N + col];
                float2 s1 = *(const float2*)&resid[(size_t)(rg+8)*N + col];
                v0.x += s0.x; v0.y += s0.y; v1.x += s1.x; v1.y += s1.y;
            }
            *(float2*)&Cm[(size_t)rg*N + col]     = v0;
            *(float2*)&Cm[(size_t)(rg+8)*N + col] = v1;
        }
    }
}

// ---------------- RoPE (in-place on q and k halves of g_qkv) ----------------
__global__ __launch_bounds__(256) void rope_kernel(
    const float* __restrict__ cosb, const float* __restrict__ sinb)
{
    const int NQ = BTn * Hn * 32;                    // 2^21 pairs per tensor
    int idx = blockIdx.x * 256 + threadIdx.x;        // 0 .. 2*NQ-1
    float* buf = g_qkv + (idx >= NQ ? (size_t)BTn * Cn : 0);
    int i  = idx & (NQ - 1);
    int d  = i & 31;
    int bh = i >> 5;                                  // (b*T + t)*H + h
    int t  = (bh >> 4) & (Tn - 1);
    size_t base = (size_t)bh * 64;
    float x1 = buf[base + d];
    float x2 = buf[base + d + 32];
    float c1 = cosb[t*64 + d],      s1 = sinb[t*64 + d];
    float c2 = cosb[t*64 + d + 32], s2 = sinb[t*64 + d + 32];
    buf[base + d]      = x1 * c1 - x2 * s1;
    buf[base + d + 32] = x2 * c2 + x1 * s2;
}

// ---------------- tensor-core causal flash attention (tf32 warp MMA) ----------
#define PK 67
#define PV 68
#define PP 68
#define SMEM_ATTN ((64*PK + 64*PV + 64*PP) * 4)

__global__ __launch_bounds__(128, 3) void attn_mma(
    const float* __restrict__ q, const float* __restrict__ k,
    const float* __restrict__ v, float* __restrict__ y)
{
    extern __shared__ float sm[];
    float* Ks = sm;
    float* Vs = Ks + 64*PK;
    float* Ps = Vs + 64*PV;

    const int tid = threadIdx.x;
    const int w = tid >> 5, lane = tid & 31, grp = lane >> 2, tig = lane & 3;
    const int wm = w * 16;
    const int bh = blockIdx.y, b = bh >> 4, h = bh & 15;
    const int bq = (gridDim.x - 1 - blockIdx.x) * 64;     // longest blocks first

    const int rowstride = Hn * Dn;                         // 1024
    const size_t base = ((size_t)b * Tn * Hn + h) * Dn;

    const float qscale = 0.125f * 1.44269504088896341f;
#pragma unroll
    for (int i = 0; i < 8; i++) {
        int linear = (i*128 + tid) * 4;
        int row = linear >> 6, col = linear & 63;
        float4 t4 = *(const float4*)&q[base + (size_t)(bq + row) * rowstride + col];
        float* dst = &Ps[row*PP + col];
        dst[0] = t4.x*qscale; dst[1] = t4.y*qscale; dst[2] = t4.z*qscale; dst[3] = t4.w*qscale;
    }
    __syncthreads();
    uint32_t qa[8][4];
#pragma unroll
    for (int kb = 0; kb < 8; kb++) {
        qa[kb][0] = f2tf32(Ps[(wm+grp)  *PP + kb*8 + tig]);
        qa[kb][1] = f2tf32(Ps[(wm+grp+8)*PP + kb*8 + tig]);
        qa[kb][2] = f2tf32(Ps[(wm+grp)  *PP + kb*8 + tig + 4]);
        qa[kb][3] = f2tf32(Ps[(wm+grp+8)*PP + kb*8 + tig + 4]);
    }
    __syncthreads();

    float o[8][4];
#pragma unroll
    for (int dt = 0; dt < 8; dt++)
#pragma unroll
        for (int i = 0; i < 4; i++) o[dt][i] = 0.f;
    float m0 = -1e30f, m1 = -1e30f, l0 = 0.f, l1 = 0.f;

    const int ktE = bq >> 6;
    for (int kt = 0; kt <= ktE; kt++) {
#pragma unroll
        for (int i = 0; i < 8; i++) {
            int linear = (i*128 + tid) * 4;
            int row = linear >> 6, col = linear & 63;
            size_t gof = base + (size_t)(kt*64 + row) * rowstride + col;
            float4 kv = *(const float4*)&k[gof];
            Ks[(col+0)*PK + row] = kv.x;
            Ks[(col+1)*PK + row] = kv.y;
            Ks[(col+2)*PK + row] = kv.z;
            Ks[(col+3)*PK + row] = kv.w;
            *(float4*)&Vs[row*PV + col] = *(const float4*)&v[gof];
        }
        __syncthreads();

        float s[8][4];
#pragma unroll
        for (int nt = 0; nt < 8; nt++) {
            s[nt][0] = 0.f; s[nt][1] = 0.f; s[nt][2] = 0.f; s[nt][3] = 0.f;
#pragma unroll
            for (int kb = 0; kb < 8; kb++) {
                uint32_t b0 = fu(Ks[(kb*8 + tig)    *PK + nt*8 + grp]);
                uint32_t b1 = fu(Ks[(kb*8 + tig + 4)*PK + nt*8 + grp]);
                mma8(s[nt], qa[kb][0], qa[kb][1], qa[kb][2], qa[kb][3], b0, b1);
            }
        }

        if (kt == ktE) {
#pragma unroll
            for (int nt = 0; nt < 8; nt++) {
                int coll = nt*8 + 2*tig;
                if (coll     > wm + grp)     s[nt][0] = -1e30f;
                if (coll + 1 > wm + grp)     s[nt][1] = -1e30f;
                if (coll     > wm + grp + 8) s[nt][2] = -1e30f;
                if (coll + 1 > wm + grp + 8) s[nt][3] = -1e30f;
            }
        }

        float t0 = -1e30f, t1 = -1e30f;
#pragma unroll
        for (int nt = 0; nt < 8; nt++) {
            t0 = fmaxf(t0, fmaxf(s[nt][0], s[nt][1]));
            t1 = fmaxf(t1, fmaxf(s[nt][2], s[nt][3]));
        }
        t0 = fmaxf(t0, __shfl_xor_sync(0xffffffffu, t0, 1));
        t0 = fmaxf(t0, __shfl_xor_sync(0xffffffffu, t0, 2));
        t1 = fmaxf(t1, __shfl_xor_sync(0xffffffffu, t1, 1));
        t1 = fmaxf(t1, __shfl_xor_sync(0xffffffffu, t1, 2));
        float m0n = fmaxf(m0, t0), m1n = fmaxf(m1, t1);
        float scl0 = exp2c(m0 - m0n), scl1 = exp2c(m1 - m1n);
        m0 = m0n; m1 = m1n;
        float lp0 = 0.f, lp1 = 0.f;
#pragma unroll
        for (int nt = 0; nt < 8; nt++) {
            s[nt][0] = exp2c(s[nt][0] - m0); s[nt][1] = exp2c(s[nt][1] - m0);
            s[nt][2] = exp2c(s[nt][2] - m1); s[nt][3] = exp2c(s[nt][3] - m1);
            lp0 += s[nt][0] + s[nt][1];
            lp1 += s[nt][2] + s[nt][3];
        }
        l0 = l0 * scl0 + lp0;
        l1 = l1 * scl1 + lp1;
#pragma unroll
        for (int dt = 0; dt < 8; dt++) {
            o[dt][0] *= scl0; o[dt][1] *= scl0; o[dt][2] *= scl1; o[dt][3] *= scl1;
        }

#pragma unroll
        for (int nt = 0; nt < 8; nt++) {
            *(float2*)&Ps[(wm+grp)  *PP + nt*8 + 2*tig] = make_float2(s[nt][0], s[nt][1]);
            *(float2*)&Ps[(wm+grp+8)*PP + nt*8 + 2*tig] = make_float2(s[nt][2], s[nt][3]);
        }
        __syncwarp();

#pragma unroll
        for (int kb = 0; kb < 8; kb++) {
            uint32_t a0 = fu(Ps[(wm+grp)  *PP + kb*8 + tig]);
            uint32_t a1 = fu(Ps[(wm+grp+8)*PP + kb*8 + tig]);
            uint32_t a2 = fu(Ps[(wm+grp)  *PP + kb*8 + tig + 4]);
            uint32_t a3 = fu(Ps[(wm+grp+8)*PP + kb*8 + tig + 4]);
#pragma unroll
            for (int dt = 0; dt < 8; dt++) {
                uint32_t b0 = fu(Vs[(kb*8 + tig)    *PV + dt*8 + grp]);
                uint32_t b1 = fu(Vs[(kb*8 + tig + 4)*PV + dt*8 + grp]);
                mma8(o[dt], a0, a1, a2, a3, b0, b1);
            }
        }
        __syncthreads();
    }

    l0 += __shfl_xor_sync(0xffffffffu, l0, 1);
    l0 += __shfl_xor_sync(0xffffffffu, l0, 2);
    l1 += __shfl_xor_sync(0xffffffffu, l1, 1);
    l1 += __shfl_xor_sync(0xffffffffu, l1, 2);
    const float inv0 = 1.f / l0, inv1 = 1.f / l1;
    const int r0g = bq + wm + grp, r1g = r0g + 8;
#pragma unroll
    for (int dt = 0; dt < 8; dt++) {
        const int col = dt*8 + 2*tig;
        *(float2*)&y[base + (size_t)r0g*rowstride + col] =
            make_float2(o[dt][0]*inv0, o[dt][1]*inv0);
        *(float2*)&y[base + (size_t)r1g*rowstride + col] =
            make_float2(o[dt][2]*inv1, o[dt][3]*inv1);
    }
}

// ---------------- router ----------------
__global__ __launch_bounds__(256) void router_kernel(
    const float* __restrict__ hn, const float* __restrict__ rw)
{
    const int t = blockIdx.x;
    const int tid = threadIdx.x;
    const int lane = tid & 31, w = tid >> 5;
    __shared__ float logits[8];
    const float* xp = hn + (size_t)t * Cn;
    const float* wp = rw + (size_t)w * Cn;
    float s = 0.f;
    for (int c = lane; c < Cn; c += 32) s = fmaf(xp[c], wp[c], s);
#pragma unroll
    for (int off = 16; off > 0; off >>= 1) s += __shfl_xor_sync(0xffffffffu, s, off);
    if (lane == 0) logits[w] = s;
    __syncthreads();
    if (tid == 0) {
        float l0 = logits[0]; int e0 = 0;
#pragma unroll
        for (int e = 1; e < 8; e++) if (logits[e] > l0) { l0 = logits[e]; e0 = e; }
        float l1 = -INFINITY; int e1 = 0;
#pragma unroll
        for (int e = 0; e < 8; e++) if (e != e0 && logits[e] > l1) { l1 = logits[e]; e1 = e; }
        float g0 = 1.f / (1.f + __expf(l1 - l0));
        float g1 = 1.f - g0;
        int p0 = atomicAdd(&g_counts[e0], 1);
        g_tok[e0*4096 + p0] = t; g_gate[e0*4096 + p0] = g0;
        int p1 = atomicAdd(&g_counts[e1], 1);
        g_tok[e1*4096 + p1] = t; g_gate[e1*4096 + p1] = g1;
    }
}

// ---------------- MoE GEMM1 (bf16): G = silu(X@w1^T)*(X@w3^T), gathered rows ----
// 128x64 block, 8 warps (4m x 2n), warp tile 32x32, dual accumulators.
__global__ __launch_bounds__(256, 2) void moe_gemm1_bf16(
    const float* __restrict__ w1, const float* __restrict__ w3)
{
    const int e = blockIdx.z;
    const int cnt = g_counts[e];
    const int bm = blockIdx.y * 128;
    if (bm >= cnt) return;
    const int bn = blockIdx.x * 64;
    __shared__ uint32_t As[2][8][PA];
    __shared__ uint32_t B1s[2][8][PB];
    __shared__ uint32_t B3s[2][8][PB];
    __shared__ int rowtok[128];
    const int tid = threadIdx.x;
    if (tid < 128) {
        int r = bm + tid;
        rowtok[tid] = g_tok[e*4096 + ((r < cnt) ? r : 0)];
    }
    __syncthreads();
    const float* W1 = w1 + (size_t)e * HDn * Cn;
    const float* W3 = w3 + (size_t)e * HDn * Cn;
    const int w = tid >> 5, lane = tid & 31, grp = lane >> 2, tig = lane & 3;
    const int wm = (w & 3) * 32, wn = (w >> 2) * 32;

    const int r0 = tid >> 2, c40 = (tid & 3) << 2, k20 = (tid & 3) << 1;
    const float* Ap0 = g_h + (size_t)rowtok[r0]      * Cn + c40;
    const float* Ap1 = g_h + (size_t)rowtok[r0 + 64] * Cn + c40;
    const float* B1p = W1  + (size_t)(bn + r0) * Cn + c40;
    const float* B3p = W3  + (size_t)(bn + r0) * Cn + c40;

    float acc1[2][4][4], acc3[2][4][4];
#pragma unroll
    for (int mt = 0; mt < 2; mt++)
#pragma unroll
        for (int nt = 0; nt < 4; nt++)
#pragma unroll
            for (int i = 0; i < 4; i++) { acc1[mt][nt][i] = 0.f; acc3[mt][nt][i] = 0.f; }

    float4 ra0 = *(const float4*)Ap0, ra1 = *(const float4*)Ap1;
    float4 rb1 = *(const float4*)B1p, rb3 = *(const float4*)B3p;
    STSB(As[0], k20, r0, ra0); STSB(As[0], k20, r0 + 64, ra1);
    STSB(B1s[0], k20, r0, rb1); STSB(B3s[0], k20, r0, rb3);
    __syncthreads();

    const int NT = Cn >> 4;
    for (int kt = 0; kt < NT; kt++) {
        const int cur = kt & 1;
        if (kt + 1 < NT) {
            const int ko = (kt + 1) << 4;
            ra0 = *(const float4*)(Ap0 + ko); ra1 = *(const float4*)(Ap1 + ko);
            rb1 = *(const float4*)(B1p + ko); rb3 = *(const float4*)(B3p + ko);
        }
        {
            uint32_t bf1[4][2], bf3[4][2];
#pragma unroll
            for (int nt = 0; nt < 4; nt++) {
                const int n0 = wn + nt*8 + grp;
                bf1[nt][0] = B1s[cur][tig][n0];
                bf1[nt][1] = B1s[cur][tig + 4][n0];
                bf3[nt][0] = B3s[cur][tig][n0];
                bf3[nt][1] = B3s[cur][tig + 4][n0];
            }
#pragma unroll
            for (int mt = 0; mt < 2; mt++) {
                const int m0 = wm + mt*16 + grp;
                uint32_t a0 = As[cur][tig][m0];
                uint32_t a1 = As[cur][tig][m0 + 8];
                uint32_t a2 = As[cur][tig + 4][m0];
                uint32_t a3 = As[cur][tig + 4][m0 + 8];
#pragma unroll
                for (int nt = 0; nt < 4; nt++) {
                    mma16(acc1[mt][nt], a0, a1, a2, a3, bf1[nt][0], bf1[nt][1]);
                    mma16(acc3[mt][nt], a0, a1, a2, a3, bf3[nt][0], bf3[nt][1]);
                }
            }
        }
        if (kt + 1 < NT) {
            const int nx = cur ^ 1;
            STSB(As[nx], k20, r0, ra0); STSB(As[nx], k20, r0 + 64, ra1);
            STSB(B1s[nx], k20, r0, rb1); STSB(B3s[nx], k20, r0, rb3);
        }
        __syncthreads();
    }
#pragma unroll
    for (int mt = 0; mt < 2; mt++) {
#pragma unroll
        for (int half = 0; half < 2; half++) {
            const int rl = wm + mt*16 + grp + half*8;
            if (bm + rl < cnt) {
                float* gp = &g_g[((size_t)e*4096 + bm + rl)*HDn + bn];
#pragma unroll
                for (int nt = 0; nt < 4; nt++) {
                    const int col = wn + nt*8 + 2*tig;
                    float u0 = acc1[mt][nt][2*half+0], v0 = acc3[mt][nt][2*half+0];
                    float u1 = acc1[mt][nt][2*half+1], v1 = acc3[mt][nt][2*half+1];
                    float g0 = u0 / (1.f + __expf(-u0)) * v0;
                    float g1 = u1 / (1.f + __expf(-u1)) * v1;
                    *(float2*)&gp[col] = make_float2(g0, g1);
                }
            }
        }
    }
}

// ---------------- MoE GEMM2 (bf16): Y = G @ w2^T, gated scatter-add -----------
__global__ __launch_bounds__(256, 2) void moe_gemm2_bf16(const float* __restrict__ w2)
{
    const int e = blockIdx.z;
    const int cnt = g_counts[e];
    const int bm = blockIdx.y * 128;
    if (bm >= cnt) return;
    const int bn = blockIdx.x * 128;
    __shared__ uint32_t As[2][8][PA];
    __shared__ uint32_t Bs[2][8][PA];
    const float* Am = g_g + (size_t)e * 4096 * HDn;
    const float* Bmat = w2 + (size_t)e * Cn * HDn;
    const int tid = threadIdx.x;
    const int w = tid >> 5, lane = tid & 31, grp = lane >> 2, tig = lane & 3;
    const int wm = (w & 1) * 64, wn = (w >> 1) * 32;

    const int r0 = tid >> 2, c40 = (tid & 3) << 2, k20 = (tid & 3) << 1;
    const float* Ap0 = Am   + (size_t)(bm + r0)      * HDn + c40;
    const float* Ap1 = Am   + (size_t)(bm + r0 + 64) * HDn + c40;
    const float* Bp0 = Bmat + (size_t)(bn + r0)      * HDn + c40;
    const float* Bp1 = Bmat + (size_t)(bn + r0 + 64) * HDn + c40;

    float acc[4][4][4];
#pragma unroll
    for (int mt = 0; mt < 4; mt++)
#pragma unroll
        for (int nt = 0; nt < 4; nt++)
#pragma unroll
            for (int i = 0; i < 4; i++) acc[mt][nt][i] = 0.f;

    float4 ra0 = *(const float4*)Ap0, ra1 = *(const float4*)Ap1;
    float4 rb0 = *(const float4*)Bp0, rb1 = *(const float4*)Bp1;
    STSB(As[0], k20, r0, ra0); STSB(As[0], k20, r0 + 64, ra1);
    STSB(Bs[0], k20, r0, rb0); STSB(Bs[0], k20, r0 + 64, rb1);
    __syncthreads();

    const int NT = HDn >> 4;
    for (int kt = 0; kt < NT; kt++) {
        const int cur = kt & 1;
        if (kt + 1 < NT) {
            const int ko = (kt + 1) << 4;
            ra0 = *(const float4*)(Ap0 + ko); ra1 = *(const float4*)(Ap1 + ko);
            rb0 = *(const float4*)(Bp0 + ko); rb1 = *(const float4*)(Bp1 + ko);
        }
        {
            uint32_t bf[4][2];
#pragma unroll
            for (int nt = 0; nt < 4; nt++) {
                const int n0 = wn + nt*8 + grp;
                bf[nt][0] = Bs[cur][tig][n0];
                bf[nt][1] = Bs[cur][tig + 4][n0];
            }
#pragma unroll
            for (int mt = 0; mt < 4; mt++) {
                const int m0 = wm + mt*16 + grp;
                uint32_t a0 = As[cur][tig][m0];
                uint32_t a1 = As[cur][tig][m0 + 8];
                uint32_t a2 = As[cur][tig + 4][m0];
                uint32_t a3 = As[cur][tig + 4][m0 + 8];
#pragma unroll
                for (int nt = 0; nt < 4; nt++)
                    mma16(acc[mt][nt], a0, a1, a2, a3, bf[nt][0], bf[nt][1]);
            }
        }
        if (kt + 1 < NT) {
            const int nx = cur ^ 1;
            STSB(As[nx], k20, r0, ra0); STSB(As[nx], k20, r0 + 64, ra1);
            STSB(Bs[nx], k20, r0, rb0); STSB(Bs[nx], k20, r0 + 64, rb1);
        }
        __syncthreads();
    }
#pragma unroll
    for (int mt = 0; mt < 4; mt++) {
#pragma unroll
        for (int half = 0; half < 2; half++) {
            const int rl = wm + mt*16 + grp + half*8;
            if (bm + rl < cnt) {
                const int tok = g_tok[e*4096 + bm + rl];
                const float gt = g_gate[e*4096 + bm + rl];
                float* mp = &g_moe[(size_t)tok*Cn + bn];
#pragma unroll
                for (int nt = 0; nt < 4; nt++) {
                    const int col = wn + nt*8 + 2*tig;
                    atomicAdd(&mp[col],     gt * acc[mt][nt][2*half+0]);
                    atomicAdd(&mp[col + 1], gt * acc[mt][nt][2*half+1]);
                }
            }
        }
    }
}

// ---------------- final: out += moe ----------------
__global__ void final_add(float* __restrict__ out) {
    int i = blockIdx.x * 256 + threadIdx.x;
    float4 a = ((float4*)out)[i];
    float4 bb = ((const float4*)g_moe)[i];
    a.x += bb.x; a.y += bb.y; a.z += bb.z; a.w += bb.w;
    ((float4*)out)[i] = a;
}

// ---------------- launch ----------------
extern "C" void kernel_launch(void* const* d_in, const int* in_sizes, int n_in,
                              void* d_out, int out_size)
{
    const float* x        = (const float*)d_in[0];
    const float* rope_cos = (const float*)d_in[1];
    const float* rope_sin = (const float*)d_in[2];
    const float* attn_nw  = (const float*)d_in[3];
    const float* q_w      = (const float*)d_in[4];
    const float* k_w      = (const float*)d_in[5];
    const float* v_w      = (const float*)d_in[6];
    const float* o_w      = (const float*)d_in[7];
    const float* ffn_nw   = (const float*)d_in[8];
    const float* router_w = (const float*)d_in[9];
    const float* w1       = (const float*)d_in[10];
    const float* w2       = (const float*)d_in[11];
    const float* w3       = (const float*)d_in[12];
    float* out = (float*)d_out;

    float *p_h, *p_qkv, *p_y;
    cudaGetSymbolAddress((void**)&p_h,   g_h);
    cudaGetSymbolAddress((void**)&p_qkv, g_qkv);
    cudaGetSymbolAddress((void**)&p_y,   g_y);

    static int attn_attr_set = 0;
    if (!attn_attr_set) {
        cudaFuncSetAttribute(attn_mma, cudaFuncAttributeMaxDynamicSharedMemorySize, SMEM_ATTN);
        attn_attr_set = 1;
    }

    // 1. zero moe accumulator + expert counters
    zero_kernel<<<(BTn*Cn/4)/256, 256>>>();
    // 2. attention rmsnorm
    rmsnorm_kernel<<<BTn, 256>>>(x, attn_nw, p_h);
    // 3. fused QKV projection (bf16 tensor cores; z selects weight/output)
    gemm_bf16<<<dim3(Cn/128, BTn/128, 3), 256>>>(p_h, q_w, k_w, v_w,
                                                 p_qkv, (size_t)BTn*Cn, nullptr, Cn, Cn);
    // 4. RoPE on q and k
    rope_kernel<<<(2*BTn*Hn*32)/256, 256>>>(rope_cos, rope_sin);
    // 5. causal flash attention (tf32 warp MMA)
    attn_mma<<<dim3(Tn/64, Bn*Hn), 128, SMEM_ATTN>>>(p_qkv, p_qkv + (size_t)BTn*Cn,
                                                     p_qkv + 2*(size_t)BTn*Cn, p_y);
    // 6. O projection + residual -> d_out
    gemm_bf16<<<dim3(Cn/128, BTn/128, 1), 256>>>(p_y, o_w, o_w, o_w,
                                                 out, 0, x, Cn, Cn);
    // 7. ffn rmsnorm (reuse g_h)
    rmsnorm_kernel<<<BTn, 256>>>(out, ffn_nw, p_h);
    // 8. router: top-2 + scatter
    router_kernel<<<BTn, 256>>>(p_h, router_w);
    // 9. expert up-projections (fused w1/w3 + silu gate)
    moe_gemm1_bf16<<<dim3(HDn/64, 4096/128, En), 256>>>(w1, w3);
    // 10. expert down-projection + gated scatter-add
    moe_gemm2_bf16<<<dim3(Cn/128, 4096/128, En), 256>>>(w2);
    // 11. out += moe
    final_add<<<(BTn*Cn/4)/256, 256>>>(out);
}